// round 6
// baseline (speedup 1.0000x reference)
#include <cuda_runtime.h>
#include <math.h>
#include <stdint.h>

#define NMAX  50000
#define EMAX  800000
#define NGR   128

typedef unsigned long long u2;   // packed f32x2 (lo = edge a, hi = edge b)

// ---------------- scratch (static device arrays: no allocations) ----------------
__device__ float g_raw[(size_t)NMAX * 128];   // pre-activation node features (N,4,32)
__device__ float g_act[(size_t)NMAX * 128];   // post-activation node features (N,4,32)
__device__ float g_h3 [(size_t)NMAX * 32];    // layer-3 scalar output (N,32)
__device__ float g_pool[NGR * 32];            // graph pooled (128,32)

// ---------------- f32x2 helpers ----------------
__device__ __forceinline__ u2 pk2(float lo, float hi) {
    u2 r; asm("mov.b64 %0, {%1,%2};" : "=l"(r) : "f"(lo), "f"(hi)); return r;
}
__device__ __forceinline__ u2 dup2(float v) {
    u2 r; asm("mov.b64 %0, {%1,%1};" : "=l"(r) : "f"(v)); return r;
}
__device__ __forceinline__ void upk(float& lo, float& hi, u2 v) {
    asm("mov.b64 {%0,%1}, %2;" : "=f"(lo), "=f"(hi) : "l"(v));
}
__device__ __forceinline__ u2 fma2(u2 a, u2 b, u2 c) {
    u2 d; asm("fma.rn.f32x2 %0, %1, %2, %3;" : "=l"(d) : "l"(a), "l"(b), "l"(c)); return d;
}
__device__ __forceinline__ u2 mul2(u2 a, u2 b) {
    u2 d; asm("mul.rn.f32x2 %0, %1, %2;" : "=l"(d) : "l"(a), "l"(b)); return d;
}
__device__ __forceinline__ u2 neg2(u2 a) { return a ^ 0x8000000080000000ULL; }
__device__ __forceinline__ u2 dupc(float v) {   // compile-time constant dup
    u2 b = (u2)__float_as_uint(v); return b | (b << 32);
}

// ---------------- scalar helpers ----------------
__device__ __forceinline__ float sspf(float x) {
    return fmaxf(x, 0.f) + log1pf(__expf(-fabsf(x))) - 0.69314718055994530942f;
}
__device__ __forceinline__ void red_add(float* p, float v) {
    asm volatile("red.global.add.f32 [%0], %1;" :: "l"(p), "f"(v) : "memory");
}
__device__ __forceinline__ float cutoff_w(float d) {
    float u = d * (1.0f / 1.5f);
    if (u >= 1.f) return 0.f;
    float u2v = u * u;
    float u6 = u2v * u2v * u2v;
    return 1.f + u6 * (-28.f + u * (48.f - 21.f * u));
}
__device__ __forceinline__ float emb_lane(float d, int lane) {
    if (lane >= 10) return 0.f;
    float mu = 0.7f + (float)lane * 0.111111111111111111f;
    float t = d - mu;
    return __expf(-50.f * t * t);
}

// ---------------- common per-warp edge loads (vectorized fast path) ----------------
// fs[9*e + c] = edge_sh component c of edge (e0+e). All indices constant after unroll.
#define LOAD_EDGES                                                              \
    int warp = (blockIdx.x * blockDim.x + threadIdx.x) >> 5;                    \
    int lane = threadIdx.x & 31;                                                \
    int e0 = warp * 4;                                                          \
    if (e0 >= E) return;                                                        \
    int src[4], dst[4];                                                         \
    float ew[4], embv[4];                                                       \
    float fs[36];                                                               \
    if (((E & 3) == 0) && (e0 + 4 <= E)) {                                      \
        int4 s4 = *(const int4*)(ei + e0);                                      \
        int4 d4 = *(const int4*)(ei + E + e0);                                  \
        float4 l4 = *(const float4*)(elen + e0);                                \
        src[0] = s4.x; src[1] = s4.y; src[2] = s4.z; src[3] = s4.w;             \
        dst[0] = d4.x; dst[1] = d4.y; dst[2] = d4.z; dst[3] = d4.w;             \
        float ls[4] = {l4.x, l4.y, l4.z, l4.w};                                 \
        _Pragma("unroll")                                                       \
        for (int e = 0; e < 4; e++) {                                           \
            ew[e] = cutoff_w(ls[e]);                                            \
            embv[e] = emb_lane(ls[e], lane);                                    \
        }                                                                       \
        const float4* q4p = (const float4*)(esh + (size_t)e0 * 9);              \
        _Pragma("unroll")                                                       \
        for (int j = 0; j < 9; j++) {                                           \
            float4 q = q4p[j];                                                  \
            fs[4 * j] = q.x; fs[4 * j + 1] = q.y;                               \
            fs[4 * j + 2] = q.z; fs[4 * j + 3] = q.w;                           \
        }                                                                       \
    } else {                                                                    \
        _Pragma("unroll")                                                       \
        for (int e = 0; e < 4; e++) {                                           \
            int idx = e0 + e;                                                   \
            bool v = idx < E;                                                   \
            int id2 = v ? idx : (E - 1);                                        \
            src[e] = ei[id2]; dst[e] = ei[E + id2];                             \
            float d = elen[id2];                                                \
            ew[e] = v ? cutoff_w(d) : 0.f;                                      \
            embv[e] = emb_lane(d, lane);                                        \
            _Pragma("unroll")                                                   \
            for (int c = 0; c < 9; c++) fs[9 * e + c] = esh[(size_t)id2 * 9 + c]; \
        }                                                                       \
    }

// ---------------- layer 1 ----------------
__global__ void __launch_bounds__(256) k_layer1(
    const float* __restrict__ x, const float* __restrict__ esh,
    const float* __restrict__ elen, const int* __restrict__ ei,
    const float* __restrict__ W1, const float* __restrict__ b1, int E)
{
    LOAD_EDGES

    u2 wa[2], wb[2];
    { u2 b0 = dup2(b1[lane]), bv = dup2(b1[32 + lane]); wa[0] = wa[1] = b0; wb[0] = wb[1] = bv; }
    #pragma unroll
    for (int k = 0; k < 10; k++) {
        u2 w0 = dup2(W1[k * 64 + lane]);
        u2 w1 = dup2(W1[k * 64 + 32 + lane]);
        #pragma unroll
        for (int pr = 0; pr < 2; pr++) {
            float ea = __shfl_sync(0xffffffffu, embv[2 * pr], k);
            float eb = __shfl_sync(0xffffffffu, embv[2 * pr + 1], k);
            u2 ekp = pk2(ea, eb);
            wa[pr] = fma2(ekp, w0, wa[pr]);
            wb[pr] = fma2(ekp, w1, wb[pr]);
        }
    }

    #pragma unroll
    for (int pr = 0; pr < 2; pr++) {
        u2 s0  = pk2(fs[pr * 18 + 0], fs[pr * 18 + 9]);
        u2 sv0 = pk2(fs[pr * 18 + 1], fs[pr * 18 + 10]);
        u2 sv1 = pk2(fs[pr * 18 + 2], fs[pr * 18 + 11]);
        u2 sv2 = pk2(fs[pr * 18 + 3], fs[pr * 18 + 12]);
        u2 xs  = pk2(x[src[2 * pr]] * ew[2 * pr], x[src[2 * pr + 1]] * ew[2 * pr + 1]);

        u2 ms = mul2(mul2(xs, s0), wa[pr]);
        u2 xw = mul2(xs, wb[pr]);
        u2 m1 = mul2(xw, sv0);
        u2 m2 = mul2(xw, sv1);
        u2 m3 = mul2(xw, sv2);

        float lo, hi;
        float* pa = g_raw + (size_t)dst[2 * pr] * 128 + lane;
        float* pb = g_raw + (size_t)dst[2 * pr + 1] * 128 + lane;
        upk(lo, hi, ms); red_add(pa,      lo); red_add(pb,      hi);
        upk(lo, hi, m1); red_add(pa + 32, lo); red_add(pb + 32, hi);
        upk(lo, hi, m2); red_add(pa + 64, lo); red_add(pb + 64, hi);
        upk(lo, hi, m3); red_add(pa + 96, lo); red_add(pb + 96, hi);
    }
}

// ---------------- norm-act ----------------
__global__ void k_normact(int N, int zero_raw)
{
    int t = blockIdx.x * blockDim.x + threadIdx.x;
    if (t >= N * 32) return;
    int n = t >> 5, c = t & 31;
    float* ip = g_raw + (size_t)n * 128;
    float s  = ip[c];
    float v0 = ip[32 + c], v1 = ip[64 + c], v2 = ip[96 + c];
    float nr = sqrtf(v0 * v0 + v1 * v1 + v2 * v2 + 1e-12f);
    float sc = sspf(nr) / nr;
    float* op = g_act + (size_t)n * 128;
    op[c]      = sspf(s);
    op[32 + c] = v0 * sc;
    op[64 + c] = v1 * sc;
    op[96 + c] = v2 * sc;
    if (zero_raw) {
        ip[c] = 0.f; ip[32 + c] = 0.f; ip[64 + c] = 0.f; ip[96 + c] = 0.f;
    }
}

// ---------------- layer 2 ----------------
__global__ void __launch_bounds__(256) k_layer2(
    const float* __restrict__ esh, const float* __restrict__ elen,
    const int* __restrict__ ei, const float* __restrict__ W2,
    const float* __restrict__ b2, int E)
{
    LOAD_EDGES

    u2 wp[2][6];
    #pragma unroll
    for (int p = 0; p < 6; p++) {
        u2 bv = dup2(b2[p * 32 + lane]);
        wp[0][p] = bv; wp[1][p] = bv;
    }
    #pragma unroll
    for (int k = 0; k < 10; k++) {
        u2 w[6];
        #pragma unroll
        for (int p = 0; p < 6; p++) w[p] = dup2(W2[k * 192 + p * 32 + lane]);
        #pragma unroll
        for (int pr = 0; pr < 2; pr++) {
            float ea = __shfl_sync(0xffffffffu, embv[2 * pr], k);
            float eb = __shfl_sync(0xffffffffu, embv[2 * pr + 1], k);
            u2 ekp = pk2(ea, eb);
            #pragma unroll
            for (int p = 0; p < 6; p++) wp[pr][p] = fma2(ekp, w[p], wp[pr][p]);
        }
    }

    const u2 C_nRT3 = dupc(-0.57735026918962576451f);  // -1/sqrt(3)
    const u2 C_nRT2 = dupc(-0.70710678118654752440f);  // -1/sqrt(2)
    const u2 C_A    = dupc( 0.31622776601683793320f);  // 1/sqrt(10)
    const u2 C_2A   = dupc( 0.63245553203367586640f);  // 2/sqrt(10)
    const u2 C_B    = dupc( 0.54772255750516611346f);  // sqrt(3/10)

    #pragma unroll
    for (int pr = 0; pr < 2; pr++) {
        u2 s0  = pk2(fs[pr * 18 + 0], fs[pr * 18 + 9]);
        u2 sv0 = pk2(fs[pr * 18 + 1], fs[pr * 18 + 10]);
        u2 sv1 = pk2(fs[pr * 18 + 2], fs[pr * 18 + 11]);
        u2 sv2 = pk2(fs[pr * 18 + 3], fs[pr * 18 + 12]);
        u2 t20 = pk2(fs[pr * 18 + 4], fs[pr * 18 + 13]);
        u2 t21 = pk2(fs[pr * 18 + 5], fs[pr * 18 + 14]);
        u2 t22 = pk2(fs[pr * 18 + 6], fs[pr * 18 + 15]);
        u2 t23 = pk2(fs[pr * 18 + 7], fs[pr * 18 + 16]);
        u2 t24 = pk2(fs[pr * 18 + 8], fs[pr * 18 + 17]);

        const float* xa = g_act + (size_t)src[2 * pr] * 128 + lane;
        const float* xb = g_act + (size_t)src[2 * pr + 1] * 128 + lane;
        u2 x0  = pk2(xa[0],  xb[0]);
        u2 xv0 = pk2(xa[32], xb[32]);
        u2 xv1 = pk2(xa[64], xb[64]);
        u2 xv2 = pk2(xa[96], xb[96]);

        u2 nxv0 = neg2(xv0), nxv1 = neg2(xv1), nxv2 = neg2(xv2);

        // paths (0,0,0) + (1,1,0)
        u2 dotv = fma2(xv2, sv2, fma2(xv1, sv1, mul2(xv0, sv0)));
        u2 m0 = fma2(mul2(dotv, C_nRT3), wp[pr][3], mul2(mul2(s0, x0), wp[pr][0]));

        // path (1,1,1): cross
        u2 cr0 = fma2(nxv2, sv1, mul2(xv1, sv2));
        u2 cr1 = fma2(nxv0, sv2, mul2(xv2, sv0));
        u2 cr2 = fma2(nxv1, sv0, mul2(xv0, sv1));

        // path (1,2,1)
        u2 axv0   = mul2(xv0, C_A);
        u2 bxv0   = mul2(xv0, C_B);
        u2 nbxv0  = neg2(bxv0);
        u2 nbxv1  = mul2(nxv1, C_B);
        u2 nbxv2  = mul2(nxv2, C_B);
        u2 n2axv1 = mul2(nxv1, C_2A);
        u2 axv2   = mul2(xv2, C_A);
        u2 t50 = fma2(nbxv2, t20, fma2(nbxv1, t21, fma2(bxv0, t24, mul2(axv0, t22))));
        u2 t51 = fma2(nbxv2, t23, fma2(n2axv1, t22, mul2(nbxv0, t21)));
        u2 t52 = fma2(nbxv2, t24, fma2(axv2, t22, fma2(nbxv1, t23, mul2(nbxv0, t20))));

        u2 x0w1 = mul2(x0, wp[pr][1]);
        u2 s0w2 = mul2(s0, wp[pr][2]);
        u2 wn4  = mul2(wp[pr][4], C_nRT2);
        u2 m1 = fma2(t50, wp[pr][5], fma2(cr0, wn4, fma2(xv0, s0w2, mul2(sv0, x0w1))));
        u2 m2 = fma2(t51, wp[pr][5], fma2(cr1, wn4, fma2(xv1, s0w2, mul2(sv1, x0w1))));
        u2 m3 = fma2(t52, wp[pr][5], fma2(cr2, wn4, fma2(xv2, s0w2, mul2(sv2, x0w1))));

        u2 ewp = pk2(ew[2 * pr], ew[2 * pr + 1]);
        m0 = mul2(m0, ewp);
        m1 = mul2(m1, ewp);
        m2 = mul2(m2, ewp);
        m3 = mul2(m3, ewp);

        float lo, hi;
        float* pa = g_raw + (size_t)dst[2 * pr] * 128 + lane;
        float* pb = g_raw + (size_t)dst[2 * pr + 1] * 128 + lane;
        upk(lo, hi, m0); red_add(pa,      lo); red_add(pb,      hi);
        upk(lo, hi, m1); red_add(pa + 32, lo); red_add(pb + 32, hi);
        upk(lo, hi, m2); red_add(pa + 64, lo); red_add(pb + 64, hi);
        upk(lo, hi, m3); red_add(pa + 96, lo); red_add(pb + 96, hi);
    }
}

// ---------------- layer 3 ----------------
__global__ void __launch_bounds__(256) k_layer3(
    const float* __restrict__ esh, const float* __restrict__ elen,
    const int* __restrict__ ei, const float* __restrict__ W3,
    const float* __restrict__ b3, int E)
{
    LOAD_EDGES

    u2 wa[2], wb[2];
    { u2 b0 = dup2(b3[lane]), bv = dup2(b3[32 + lane]); wa[0] = wa[1] = b0; wb[0] = wb[1] = bv; }
    #pragma unroll
    for (int k = 0; k < 10; k++) {
        u2 w0 = dup2(W3[k * 64 + lane]);
        u2 w1 = dup2(W3[k * 64 + 32 + lane]);
        #pragma unroll
        for (int pr = 0; pr < 2; pr++) {
            float ea = __shfl_sync(0xffffffffu, embv[2 * pr], k);
            float eb = __shfl_sync(0xffffffffu, embv[2 * pr + 1], k);
            u2 ekp = pk2(ea, eb);
            wa[pr] = fma2(ekp, w0, wa[pr]);
            wb[pr] = fma2(ekp, w1, wb[pr]);
        }
    }

    const u2 C_nRT3 = dupc(-0.57735026918962576451f);
    #pragma unroll
    for (int pr = 0; pr < 2; pr++) {
        u2 s0  = pk2(fs[pr * 18 + 0], fs[pr * 18 + 9]);
        u2 sv0 = pk2(fs[pr * 18 + 1], fs[pr * 18 + 10]);
        u2 sv1 = pk2(fs[pr * 18 + 2], fs[pr * 18 + 11]);
        u2 sv2 = pk2(fs[pr * 18 + 3], fs[pr * 18 + 12]);

        const float* xa = g_act + (size_t)src[2 * pr] * 128 + lane;
        const float* xb = g_act + (size_t)src[2 * pr + 1] * 128 + lane;
        u2 x0  = pk2(xa[0],  xb[0]);
        u2 xv0 = pk2(xa[32], xb[32]);
        u2 xv1 = pk2(xa[64], xb[64]);
        u2 xv2 = pk2(xa[96], xb[96]);

        u2 dotv = fma2(xv2, sv2, fma2(xv1, sv1, mul2(xv0, sv0)));
        u2 t = mul2(mul2(x0, s0), wa[pr]);
        u2 m = mul2(fma2(mul2(dotv, C_nRT3), wb[pr], t), pk2(ew[2 * pr], ew[2 * pr + 1]));

        float lo, hi;
        upk(lo, hi, m);
        red_add(g_h3 + (size_t)dst[2 * pr] * 32 + lane,     lo);
        red_add(g_h3 + (size_t)dst[2 * pr + 1] * 32 + lane, hi);
    }
}

// ---------------- silu + graph pooling ----------------
__global__ void k_pool(const int* __restrict__ batch, int N)
{
    int t = blockIdx.x * blockDim.x + threadIdx.x;
    if (t >= N * 32) return;
    int n = t >> 5, c = t & 31;
    float h = g_h3[(size_t)n * 32 + c];
    float y = h / (1.f + __expf(-h));
    atomicAdd(&g_pool[__ldg(&batch[n]) * 32 + c], y);
}

// ---------------- head ----------------
__global__ void k_head(const float* __restrict__ Wo, const float* __restrict__ bo,
                       float* __restrict__ out)
{
    __shared__ float Ws[32 * 8];
    __shared__ float bs[8];
    int t = threadIdx.x;
    if (t < 256) Ws[t] = Wo[t];
    if (t < 8)   bs[t] = bo[t];
    __syncthreads();
    if (t < NGR) {
        float acc[8];
        #pragma unroll
        for (int j = 0; j < 8; j++) acc[j] = bs[j];
        #pragma unroll
        for (int k = 0; k < 32; k++) {
            float gv = g_pool[t * 32 + k];
            #pragma unroll
            for (int j = 0; j < 8; j++) acc[j] = fmaf(gv, Ws[k * 8 + j], acc[j]);
        }
        float mx = acc[0];
        #pragma unroll
        for (int j = 1; j < 8; j++) mx = fmaxf(mx, acc[j]);
        float sm = 0.f;
        #pragma unroll
        for (int j = 0; j < 8; j++) { acc[j] = __expf(acc[j] - mx); sm += acc[j]; }
        float inv = 1.f / sm;
        #pragma unroll
        for (int j = 0; j < 8; j++) out[t * 8 + j] = acc[j] * inv;
    }
}

// ---------------- host ----------------
extern "C" void kernel_launch(void* const* d_in, const int* in_sizes, int n_in,
                              void* d_out, int out_size)
{
    int ix, ish, ilen, iW1, ib1, iW2, ib2, iW3, ib3, iWo, ibo, iei, ibatch;
    if (n_in >= 13 && (long long)in_sizes[1] == 9LL * (long long)in_sizes[2]) {
        ix = 0; ish = 1; ilen = 2; iW1 = 3; ib1 = 4; iW2 = 5; ib2 = 6;
        iW3 = 7; ib3 = 8; iWo = 9; ibo = 10; iei = 11; ibatch = 12;
    } else {
        ix = 0; iei = 1; ish = 2; ilen = 3; ibatch = 4; iW1 = 5; ib1 = 6;
        iW2 = 7; ib2 = 8; iW3 = 9; ib3 = 10; iWo = 11; ibo = 12;
    }

    const float* x     = (const float*)d_in[ix];
    const float* esh   = (const float*)d_in[ish];
    const float* elen  = (const float*)d_in[ilen];
    const float* W1    = (const float*)d_in[iW1];
    const float* b1    = (const float*)d_in[ib1];
    const float* W2    = (const float*)d_in[iW2];
    const float* b2    = (const float*)d_in[ib2];
    const float* W3    = (const float*)d_in[iW3];
    const float* b3    = (const float*)d_in[ib3];
    const float* Wo    = (const float*)d_in[iWo];
    const float* bo    = (const float*)d_in[ibo];
    const int*   ei    = (const int*)d_in[iei];
    const int*   batch = (const int*)d_in[ibatch];

    int N = in_sizes[ix];
    int E = in_sizes[ilen];
    if (N > NMAX) N = NMAX;
    if (E > EMAX) E = EMAX;

    void *praw, *ph3, *ppool;
    cudaGetSymbolAddress(&praw, g_raw);
    cudaGetSymbolAddress(&ph3, g_h3);
    cudaGetSymbolAddress(&ppool, g_pool);

    int nwarps = (E + 3) / 4;
    int nbE = (nwarps * 32 + 255) / 256;
    int nbN = (N * 32 + 255) / 256;

    // Layer 1
    cudaMemsetAsync(praw, 0, (size_t)N * 128 * sizeof(float), 0);
    k_layer1<<<nbE, 256>>>(x, esh, elen, ei, W1, b1, E);
    k_normact<<<nbN, 256>>>(N, /*zero_raw=*/1);

    // Layer 2
    k_layer2<<<nbE, 256>>>(esh, elen, ei, W2, b2, E);
    k_normact<<<nbN, 256>>>(N, /*zero_raw=*/0);

    // Layer 3 + pooling + head
    cudaMemsetAsync(ph3, 0, (size_t)N * 32 * sizeof(float), 0);
    cudaMemsetAsync(ppool, 0, (size_t)NGR * 32 * sizeof(float), 0);
    k_layer3<<<nbE, 256>>>(esh, elen, ei, E > 0 ? W3 : W3, b3, E);
    k_pool<<<nbN, 256>>>(batch, N);
    k_head<<<1, 256>>>(Wo, bo, (float*)d_out);
}

// round 7
// speedup vs baseline: 1.5235x; 1.5235x over previous
#include <cuda_runtime.h>
#include <math.h>
#include <stdint.h>

#define NMAX  50000
#define EMAX  800000
#define NGR   128

#define TB_BINS  3072          // bins over [0, 1.5), step 1/2048
#define TB_ROWS  (TB_BINS + 1) // guard row for interpolation
#define TB_SCALE 2048.0f
#define TB_DMAX  1.49951f      // clamp so bin <= TB_BINS-1

// ---------------- scratch (static device arrays: no allocations) ----------------
__device__ float g_raw[(size_t)NMAX * 128];   // pre-activation node features (N,4,32)
__device__ float g_act[(size_t)NMAX * 128];   // post-activation node features (N,4,32)
__device__ float g_h3 [(size_t)NMAX * 32];    // layer-3 scalar output (N,32)
__device__ float g_pool[NGR * 32];            // graph pooled (128,32)

// radial-weight tables: w'(d) = (emb(d)@W + b) * ew(d), row = bin
__device__ float g_etab[TB_ROWS * 10];        // emb per bin
__device__ float g_ewt [TB_ROWS];             // cutoff per bin
__device__ float g_tab1[(size_t)TB_ROWS * 64];
__device__ float g_tab2[(size_t)TB_ROWS * 192];
__device__ float g_tab3[(size_t)TB_ROWS * 64];

// ---------------- helpers ----------------
__device__ __forceinline__ float sspf(float x) {
    return fmaxf(x, 0.f) + log1pf(__expf(-fabsf(x))) - 0.69314718055994530942f;
}
__device__ __forceinline__ void red_add(float* p, float v) {
    asm volatile("red.global.add.f32 [%0], %1;" :: "l"(p), "f"(v) : "memory");
}
__device__ __forceinline__ float cutoff_w(float d) {
    float u = d * (1.0f / 1.5f);
    if (u >= 1.f) return 0.f;
    float u2v = u * u;
    float u6 = u2v * u2v * u2v;
    return 1.f + u6 * (-28.f + u * (48.f - 21.f * u));
}

// ---------------- table generation ----------------
__global__ void k_tab_emb()
{
    int t = blockIdx.x * blockDim.x + threadIdx.x;
    if (t < TB_ROWS) {
        float d = (float)t * (1.0f / TB_SCALE);
        g_ewt[t] = cutoff_w(d);
    }
    if (t < TB_ROWS * 10) {
        int r = t / 10, k = t - 10 * r;
        float d = (float)r * (1.0f / TB_SCALE);
        float mu = 0.7f + (float)k * 0.111111111111111111f;
        float dd = d - mu;
        g_etab[t] = __expf(-50.f * dd * dd);
    }
}

__global__ void k_tab_build(const float* __restrict__ W, const float* __restrict__ b,
                            float* __restrict__ out, int C)
{
    int t = blockIdx.x * blockDim.x + threadIdx.x;
    if (t >= TB_ROWS * C) return;
    int r = t / C, c = t - r * C;
    float v = b[c];
    #pragma unroll
    for (int k = 0; k < 10; k++)
        v = fmaf(g_etab[r * 10 + k], W[k * C + c], v);
    out[t] = v * g_ewt[r];
}

// ---------------- common per-warp edge prologue (indices, bins, validity) ----------------
#define EDGE_BINS                                                               \
    int warp = (blockIdx.x * blockDim.x + threadIdx.x) >> 5;                    \
    int lane = threadIdx.x & 31;                                                \
    int e0 = warp * 4;                                                          \
    if (e0 >= E) return;                                                        \
    int src[4], dst[4], bin[4];                                                 \
    float fr[4], vld[4];                                                        \
    _Pragma("unroll")                                                           \
    for (int e = 0; e < 4; e++) {                                               \
        int idx = e0 + e;                                                       \
        bool v = idx < E;                                                       \
        int id2 = v ? idx : (E - 1);                                            \
        src[e] = ei[id2]; dst[e] = ei[E + id2];                                 \
        float d = elen[id2];                                                    \
        vld[e] = v ? 1.f : 0.f;                                                 \
        float tt = fminf(fmaxf(d, 0.f), TB_DMAX) * TB_SCALE;                    \
        int bb = (int)tt;                                                       \
        bin[e] = bb; fr[e] = tt - (float)bb;                                    \
    }

// ---------------- layer 1 ----------------
__global__ void __launch_bounds__(256) k_layer1(
    const float* __restrict__ x, const float* __restrict__ esh,
    const float* __restrict__ elen, const int* __restrict__ ei, int E)
{
    EDGE_BINS

    // hoisted gathers (x is tiny, likely L2/L1 resident)
    float xs[4];
    #pragma unroll
    for (int e = 0; e < 4; e++) xs[e] = __ldg(&x[src[e]]) * vld[e];

    // table weights (2 paths)
    float w[4][2];
    #pragma unroll
    for (int e = 0; e < 4; e++) {
        const float* tb = g_tab1 + (size_t)bin[e] * 64 + lane;
        #pragma unroll
        for (int p = 0; p < 2; p++) {
            float v0 = __ldg(tb + p * 32);
            float v1 = __ldg(tb + 64 + p * 32);
            w[e][p] = fmaf(fr[e], v1 - v0, v0);
        }
    }

    #pragma unroll
    for (int e = 0; e < 4; e++) {
        const float* she = esh + (size_t)(e0 + e < E ? e0 + e : E - 1) * 9;
        float s0  = she[0];
        float sv0 = she[1], sv1 = she[2], sv2 = she[3];

        float* outp = g_raw + (size_t)dst[e] * 128 + lane;
        float xw0 = xs[e] * w[e][0];
        float xw1 = xs[e] * w[e][1];
        red_add(outp,      xw0 * s0);
        red_add(outp + 32, xw1 * sv0);
        red_add(outp + 64, xw1 * sv1);
        red_add(outp + 96, xw1 * sv2);
    }
}

// ---------------- norm-act ----------------
__global__ void k_normact(int N, int zero_raw)
{
    int t = blockIdx.x * blockDim.x + threadIdx.x;
    if (t >= N * 32) return;
    int n = t >> 5, c = t & 31;
    float* ip = g_raw + (size_t)n * 128;
    float s  = ip[c];
    float v0 = ip[32 + c], v1 = ip[64 + c], v2 = ip[96 + c];
    float nr = sqrtf(v0 * v0 + v1 * v1 + v2 * v2 + 1e-12f);
    float sc = sspf(nr) / nr;
    float* op = g_act + (size_t)n * 128;
    op[c]      = sspf(s);
    op[32 + c] = v0 * sc;
    op[64 + c] = v1 * sc;
    op[96 + c] = v2 * sc;
    if (zero_raw) {
        ip[c] = 0.f; ip[32 + c] = 0.f; ip[64 + c] = 0.f; ip[96 + c] = 0.f;
    }
}

// ---------------- layer 2 ----------------
__global__ void __launch_bounds__(256) k_layer2(
    const float* __restrict__ esh, const float* __restrict__ elen,
    const int* __restrict__ ei, int E)
{
    EDGE_BINS

    // hoisted gathers: 16 independent LDGs in flight
    float x0[4], xv0[4], xv1[4], xv2[4];
    #pragma unroll
    for (int e = 0; e < 4; e++) {
        const float* xp = g_act + (size_t)src[e] * 128 + lane;
        x0[e]  = __ldg(xp);
        xv0[e] = __ldg(xp + 32);
        xv1[e] = __ldg(xp + 64);
        xv2[e] = __ldg(xp + 96);
    }

    // table weights (6 paths), ew folded in
    float w[4][6];
    #pragma unroll
    for (int e = 0; e < 4; e++) {
        const float* tb = g_tab2 + (size_t)bin[e] * 192 + lane;
        #pragma unroll
        for (int p = 0; p < 6; p++) {
            float v0 = __ldg(tb + p * 32);
            float v1 = __ldg(tb + 192 + p * 32);
            w[e][p] = vld[e] * fmaf(fr[e], v1 - v0, v0);
        }
    }

    const float RT3I = 0.57735026918962576451f;  // 1/sqrt(3)
    const float RT2I = 0.70710678118654752440f;  // 1/sqrt(2)
    const float A    = 0.31622776601683793320f;  // 1/sqrt(10)
    const float B    = 0.54772255750516611346f;  // sqrt(3/10)

    #pragma unroll
    for (int e = 0; e < 4; e++) {
        const float* she = esh + (size_t)(e0 + e < E ? e0 + e : E - 1) * 9;
        float s0  = she[0];
        float sv0 = she[1], sv1 = she[2], sv2 = she[3];
        float t20 = she[4], t21 = she[5], t22 = she[6];
        float t23 = she[7], t24 = she[8];

        // paths (0,0,0) + (1,1,0)
        float dotv = xv0[e] * sv0 + xv1[e] * sv1 + xv2[e] * sv2;
        float m0 = s0 * x0[e] * w[e][0] - RT3I * dotv * w[e][3];

        // path (1,1,1): -1/sqrt2 * cross
        float cr0 = xv1[e] * sv2 - xv2[e] * sv1;
        float cr1 = xv2[e] * sv0 - xv0[e] * sv2;
        float cr2 = xv0[e] * sv1 - xv1[e] * sv0;

        // path (1,2,1): real CG(1,2,1) contraction
        float t50 =  A * xv0[e] * t22 + B * xv0[e] * t24 - B * xv1[e] * t21 - B * xv2[e] * t20;
        float t51 = -B * xv0[e] * t21 - 2.f * A * xv1[e] * t22 - B * xv2[e] * t23;
        float t52 = -B * xv0[e] * t20 - B * xv1[e] * t23 + A * xv2[e] * t22 - B * xv2[e] * t24;

        float x0w1 = x0[e] * w[e][1];
        float s0w2 = s0 * w[e][2];
        float wn4  = -RT2I * w[e][4];
        float m1 = sv0 * x0w1 + xv0[e] * s0w2 + cr0 * wn4 + t50 * w[e][5];
        float m2 = sv1 * x0w1 + xv1[e] * s0w2 + cr1 * wn4 + t51 * w[e][5];
        float m3 = sv2 * x0w1 + xv2[e] * s0w2 + cr2 * wn4 + t52 * w[e][5];

        float* outp = g_raw + (size_t)dst[e] * 128 + lane;
        red_add(outp,      m0);
        red_add(outp + 32, m1);
        red_add(outp + 64, m2);
        red_add(outp + 96, m3);
    }
}

// ---------------- layer 3 ----------------
__global__ void __launch_bounds__(256) k_layer3(
    const float* __restrict__ esh, const float* __restrict__ elen,
    const int* __restrict__ ei, int E)
{
    EDGE_BINS

    float x0[4], xv0[4], xv1[4], xv2[4];
    #pragma unroll
    for (int e = 0; e < 4; e++) {
        const float* xp = g_act + (size_t)src[e] * 128 + lane;
        x0[e]  = __ldg(xp);
        xv0[e] = __ldg(xp + 32);
        xv1[e] = __ldg(xp + 64);
        xv2[e] = __ldg(xp + 96);
    }

    float w[4][2];
    #pragma unroll
    for (int e = 0; e < 4; e++) {
        const float* tb = g_tab3 + (size_t)bin[e] * 64 + lane;
        #pragma unroll
        for (int p = 0; p < 2; p++) {
            float v0 = __ldg(tb + p * 32);
            float v1 = __ldg(tb + 64 + p * 32);
            w[e][p] = vld[e] * fmaf(fr[e], v1 - v0, v0);
        }
    }

    const float RT3I = 0.57735026918962576451f;
    #pragma unroll
    for (int e = 0; e < 4; e++) {
        const float* she = esh + (size_t)(e0 + e < E ? e0 + e : E - 1) * 9;
        float s0  = she[0];
        float sv0 = she[1], sv1 = she[2], sv2 = she[3];

        float dotv = xv0[e] * sv0 + xv1[e] * sv1 + xv2[e] * sv2;
        float m0 = x0[e] * s0 * w[e][0] - RT3I * dotv * w[e][1];

        red_add(g_h3 + (size_t)dst[e] * 32 + lane, m0);
    }
}

// ---------------- silu + graph pooling ----------------
__global__ void k_pool(const int* __restrict__ batch, int N)
{
    int t = blockIdx.x * blockDim.x + threadIdx.x;
    if (t >= N * 32) return;
    int n = t >> 5, c = t & 31;
    float h = g_h3[(size_t)n * 32 + c];
    float y = h / (1.f + __expf(-h));
    atomicAdd(&g_pool[__ldg(&batch[n]) * 32 + c], y);
}

// ---------------- head ----------------
__global__ void k_head(const float* __restrict__ Wo, const float* __restrict__ bo,
                       float* __restrict__ out)
{
    __shared__ float Ws[32 * 8];
    __shared__ float bs[8];
    int t = threadIdx.x;
    if (t < 256) Ws[t] = Wo[t];
    if (t < 8)   bs[t] = bo[t];
    __syncthreads();
    if (t < NGR) {
        float acc[8];
        #pragma unroll
        for (int j = 0; j < 8; j++) acc[j] = bs[j];
        #pragma unroll
        for (int k = 0; k < 32; k++) {
            float gv = g_pool[t * 32 + k];
            #pragma unroll
            for (int j = 0; j < 8; j++) acc[j] = fmaf(gv, Ws[k * 8 + j], acc[j]);
        }
        float mx = acc[0];
        #pragma unroll
        for (int j = 1; j < 8; j++) mx = fmaxf(mx, acc[j]);
        float sm = 0.f;
        #pragma unroll
        for (int j = 0; j < 8; j++) { acc[j] = __expf(acc[j] - mx); sm += acc[j]; }
        float inv = 1.f / sm;
        #pragma unroll
        for (int j = 0; j < 8; j++) out[t * 8 + j] = acc[j] * inv;
    }
}

// ---------------- host ----------------
extern "C" void kernel_launch(void* const* d_in, const int* in_sizes, int n_in,
                              void* d_out, int out_size)
{
    int ix, ish, ilen, iW1, ib1, iW2, ib2, iW3, ib3, iWo, ibo, iei, ibatch;
    if (n_in >= 13 && (long long)in_sizes[1] == 9LL * (long long)in_sizes[2]) {
        ix = 0; ish = 1; ilen = 2; iW1 = 3; ib1 = 4; iW2 = 5; ib2 = 6;
        iW3 = 7; ib3 = 8; iWo = 9; ibo = 10; iei = 11; ibatch = 12;
    } else {
        ix = 0; iei = 1; ish = 2; ilen = 3; ibatch = 4; iW1 = 5; ib1 = 6;
        iW2 = 7; ib2 = 8; iW3 = 9; ib3 = 10; iWo = 11; ibo = 12;
    }

    const float* x     = (const float*)d_in[ix];
    const float* esh   = (const float*)d_in[ish];
    const float* elen  = (const float*)d_in[ilen];
    const float* W1    = (const float*)d_in[iW1];
    const float* b1    = (const float*)d_in[ib1];
    const float* W2    = (const float*)d_in[iW2];
    const float* b2    = (const float*)d_in[ib2];
    const float* W3    = (const float*)d_in[iW3];
    const float* b3    = (const float*)d_in[ib3];
    const float* Wo    = (const float*)d_in[iWo];
    const float* bo    = (const float*)d_in[ibo];
    const int*   ei    = (const int*)d_in[iei];
    const int*   batch = (const int*)d_in[ibatch];

    int N = in_sizes[ix];
    int E = in_sizes[ilen];
    if (N > NMAX) N = NMAX;
    if (E > EMAX) E = EMAX;

    void *praw, *ph3, *ppool, *pt1, *pt2, *pt3;
    cudaGetSymbolAddress(&praw, g_raw);
    cudaGetSymbolAddress(&ph3, g_h3);
    cudaGetSymbolAddress(&ppool, g_pool);
    cudaGetSymbolAddress(&pt1, g_tab1);
    cudaGetSymbolAddress(&pt2, g_tab2);
    cudaGetSymbolAddress(&pt3, g_tab3);

    int nwarps = (E + 3) / 4;
    int nbE = (nwarps * 32 + 255) / 256;
    int nbN = (N * 32 + 255) / 256;

    // Build radial-weight tables (cutoff folded in)
    k_tab_emb<<<(TB_ROWS * 10 + 255) / 256, 256>>>();
    k_tab_build<<<(TB_ROWS * 64  + 255) / 256, 256>>>(W1, b1, (float*)pt1, 64);
    k_tab_build<<<(TB_ROWS * 192 + 255) / 256, 256>>>(W2, b2, (float*)pt2, 192);
    k_tab_build<<<(TB_ROWS * 64  + 255) / 256, 256>>>(W3, b3, (float*)pt3, 64);

    // Layer 1
    cudaMemsetAsync(praw, 0, (size_t)N * 128 * sizeof(float), 0);
    k_layer1<<<nbE, 256>>>(x, esh, elen, ei, E);
    k_normact<<<nbN, 256>>>(N, /*zero_raw=*/1);

    // Layer 2
    k_layer2<<<nbE, 256>>>(esh, elen, ei, E);
    k_normact<<<nbN, 256>>>(N, /*zero_raw=*/0);

    // Layer 3 + pooling + head
    cudaMemsetAsync(ph3, 0, (size_t)N * 32 * sizeof(float), 0);
    cudaMemsetAsync(ppool, 0, (size_t)NGR * 32 * sizeof(float), 0);
    k_layer3<<<nbE, 256>>>(esh, elen, ei, E);
    k_pool<<<nbN, 256>>>(batch, N);
    k_head<<<1, 256>>>(Wo, bo, (float*)d_out);
}

// round 8
// speedup vs baseline: 1.8079x; 1.1867x over previous
#include <cuda_runtime.h>
#include <cuda_fp16.h>
#include <math.h>
#include <stdint.h>

#define NMAX  50000
#define EMAX  800000
#define NGR   128

#define TB_BINS  3072          // bins over [0, 1.5), step 1/2048
#define TB_ROWS  (TB_BINS + 1) // guard row for interpolation
#define TB_SCALE 2048.0f
#define TB_DMAX  1.49951f      // clamp so bin <= TB_BINS-1

// ---------------- scratch (static device arrays: no allocations) ----------------
// g_raw layout: (N, 32 lanes, 4 comps) fp32  -> node stride 128 floats
__device__ float   g_raw[(size_t)NMAX * 128];
// g_act layout: (N, 32 lanes, 4 comps) fp16  -> node stride 64 half2
__device__ __half2 g_acth[(size_t)NMAX * 64];
__device__ float   g_h3 [(size_t)NMAX * 32];
__device__ float   g_pool[NGR * 32];

// radial-weight tables (cutoff folded in), fp16 path-paired
__device__ float   g_etab[TB_ROWS * 10];
__device__ float   g_ewt [TB_ROWS];
__device__ __half2 g_tab1h[(size_t)TB_ROWS * 32];       // [row][lane] = {path0, path1}
__device__ __half2 g_tab2h[(size_t)TB_ROWS * 96];       // [row][pp][lane] = {path2pp, path2pp+1}
__device__ __half2 g_tab3h[(size_t)TB_ROWS * 32];

// ---------------- helpers ----------------
__device__ __forceinline__ float sspf(float x) {
    return fmaxf(x, 0.f) + log1pf(__expf(-fabsf(x))) - 0.69314718055994530942f;
}
__device__ __forceinline__ void red_add(float* p, float v) {
    asm volatile("red.global.add.f32 [%0], %1;" :: "l"(p), "f"(v) : "memory");
}
__device__ __forceinline__ void red_add_v4(float* p, float a, float b, float c, float d) {
    asm volatile("red.global.add.v4.f32 [%0], {%1,%2,%3,%4};"
                 :: "l"(p), "f"(a), "f"(b), "f"(c), "f"(d) : "memory");
}
__device__ __forceinline__ float cutoff_w(float d) {
    float u = d * (1.0f / 1.5f);
    if (u >= 1.f) return 0.f;
    float u2v = u * u;
    float u6 = u2v * u2v * u2v;
    return 1.f + u6 * (-28.f + u * (48.f - 21.f * u));
}

// ---------------- table generation ----------------
__global__ void k_tab_emb()
{
    int t = blockIdx.x * blockDim.x + threadIdx.x;
    if (t < TB_ROWS) {
        float d = (float)t * (1.0f / TB_SCALE);
        g_ewt[t] = cutoff_w(d);
    }
    if (t < TB_ROWS * 10) {
        int r = t / 10, k = t - 10 * r;
        float d = (float)r * (1.0f / TB_SCALE);
        float mu = 0.7f + (float)k * 0.111111111111111111f;
        float dd = d - mu;
        g_etab[t] = __expf(-50.f * dd * dd);
    }
}

// builds half2 pair table: pair pp of a C-column weight matrix; npp = C/64
__global__ void k_tab_build_h(const float* __restrict__ W, const float* __restrict__ b,
                              __half2* __restrict__ out, int C, int npp)
{
    int t = blockIdx.x * blockDim.x + threadIdx.x;
    int per_row = npp * 32;
    if (t >= TB_ROWS * per_row) return;
    int r = t / per_row, rem = t - r * per_row;
    int pp = rem >> 5, lane = rem & 31;
    int c0 = (2 * pp) * 32 + lane;
    int c1 = (2 * pp + 1) * 32 + lane;
    float v0 = b[c0], v1 = b[c1];
    #pragma unroll
    for (int k = 0; k < 10; k++) {
        float e = g_etab[r * 10 + k];
        v0 = fmaf(e, W[k * C + c0], v0);
        v1 = fmaf(e, W[k * C + c1], v1);
    }
    float w = g_ewt[r];
    out[t] = __floats2half2_rn(v0 * w, v1 * w);
}

// ---------------- common per-warp edge prologue ----------------
#define EDGE_BINS                                                               \
    int warp = (blockIdx.x * blockDim.x + threadIdx.x) >> 5;                    \
    int lane = threadIdx.x & 31;                                                \
    int e0 = warp * 4;                                                          \
    if (e0 >= E) return;                                                        \
    int src[4], dst[4], bin[4];                                                 \
    float fr[4], vld[4];                                                        \
    _Pragma("unroll")                                                           \
    for (int e = 0; e < 4; e++) {                                               \
        int idx = e0 + e;                                                       \
        bool v = idx < E;                                                       \
        int id2 = v ? idx : (E - 1);                                            \
        src[e] = ei[id2]; dst[e] = ei[E + id2];                                 \
        float d = elen[id2];                                                    \
        vld[e] = v ? 1.f : 0.f;                                                 \
        float tt = fminf(fmaxf(d, 0.f), TB_DMAX) * TB_SCALE;                    \
        int bb = (int)tt;                                                       \
        bin[e] = bb; fr[e] = tt - (float)bb;                                    \
    }

// fetch fp16 feature quad for (node, lane): {x0, xv0, xv1, xv2}
__device__ __forceinline__ void gather_feat(int node, int lane,
                                            float& x0, float& xv0, float& xv1, float& xv2)
{
    const uint2* p = (const uint2*)(g_acth + (size_t)node * 64 + lane * 2);
    uint2 raw = __ldg(p);
    __half2 h01 = *reinterpret_cast<__half2*>(&raw.x);
    __half2 h23 = *reinterpret_cast<__half2*>(&raw.y);
    float2 f01 = __half22float2(h01);
    float2 f23 = __half22float2(h23);
    x0 = f01.x; xv0 = f01.y; xv1 = f23.x; xv2 = f23.y;
}

// ---------------- layer 1 ----------------
__global__ void __launch_bounds__(256) k_layer1(
    const float* __restrict__ x, const float* __restrict__ esh,
    const float* __restrict__ elen, const int* __restrict__ ei, int E)
{
    EDGE_BINS

    float xs[4];
    #pragma unroll
    for (int e = 0; e < 4; e++) xs[e] = __ldg(&x[src[e]]) * vld[e];

    float w0[4], w1[4];
    #pragma unroll
    for (int e = 0; e < 4; e++) {
        const __half2* tb = g_tab1h + (size_t)bin[e] * 32 + lane;
        float2 a = __half22float2(__ldg(tb));
        float2 b = __half22float2(__ldg(tb + 32));
        w0[e] = fmaf(fr[e], b.x - a.x, a.x);
        w1[e] = fmaf(fr[e], b.y - a.y, a.y);
    }

    #pragma unroll
    for (int e = 0; e < 4; e++) {
        const float* she = esh + (size_t)(e0 + e < E ? e0 + e : E - 1) * 9;
        float s0  = she[0];
        float sv0 = she[1], sv1 = she[2], sv2 = she[3];

        float xw0 = xs[e] * w0[e];
        float xw1 = xs[e] * w1[e];
        red_add_v4(g_raw + (size_t)dst[e] * 128 + lane * 4,
                   xw0 * s0, xw1 * sv0, xw1 * sv1, xw1 * sv2);
    }
}

// ---------------- norm-act: g_raw(f32) -> g_acth(f16), optionally zero g_raw ----------------
__global__ void k_normact(int N, int zero_raw)
{
    int t = blockIdx.x * blockDim.x + threadIdx.x;
    if (t >= N * 32) return;
    int n = t >> 5, c = t & 31;
    float4* ip = (float4*)(g_raw + (size_t)n * 128 + c * 4);
    float4 v = *ip;
    float nr = sqrtf(v.y * v.y + v.z * v.z + v.w * v.w + 1e-12f);
    float sc = sspf(nr) / nr;
    uint2 o;
    __half2 h01 = __floats2half2_rn(sspf(v.x), v.y * sc);
    __half2 h23 = __floats2half2_rn(v.z * sc, v.w * sc);
    o.x = *reinterpret_cast<unsigned*>(&h01);
    o.y = *reinterpret_cast<unsigned*>(&h23);
    *(uint2*)(g_acth + (size_t)n * 64 + c * 2) = o;
    if (zero_raw) *ip = make_float4(0.f, 0.f, 0.f, 0.f);
}

// ---------------- layer 2 ----------------
__global__ void __launch_bounds__(256) k_layer2(
    const float* __restrict__ esh, const float* __restrict__ elen,
    const int* __restrict__ ei, int E)
{
    EDGE_BINS

    float x0[4], xv0[4], xv1[4], xv2[4];
    #pragma unroll
    for (int e = 0; e < 4; e++)
        gather_feat(src[e], lane, x0[e], xv0[e], xv1[e], xv2[e]);

    float w[4][6];
    #pragma unroll
    for (int e = 0; e < 4; e++) {
        const __half2* tb = g_tab2h + (size_t)bin[e] * 96 + lane;
        #pragma unroll
        for (int pp = 0; pp < 3; pp++) {
            float2 a = __half22float2(__ldg(tb + pp * 32));
            float2 b = __half22float2(__ldg(tb + 96 + pp * 32));
            w[e][2 * pp]     = vld[e] * fmaf(fr[e], b.x - a.x, a.x);
            w[e][2 * pp + 1] = vld[e] * fmaf(fr[e], b.y - a.y, a.y);
        }
    }

    const float RT3I = 0.57735026918962576451f;  // 1/sqrt(3)
    const float RT2I = 0.70710678118654752440f;  // 1/sqrt(2)
    const float A    = 0.31622776601683793320f;  // 1/sqrt(10)
    const float B    = 0.54772255750516611346f;  // sqrt(3/10)

    #pragma unroll
    for (int e = 0; e < 4; e++) {
        const float* she = esh + (size_t)(e0 + e < E ? e0 + e : E - 1) * 9;
        float s0  = she[0];
        float sv0 = she[1], sv1 = she[2], sv2 = she[3];
        float t20 = she[4], t21 = she[5], t22 = she[6];
        float t23 = she[7], t24 = she[8];

        // paths (0,0,0) + (1,1,0)
        float dotv = xv0[e] * sv0 + xv1[e] * sv1 + xv2[e] * sv2;
        float m0 = s0 * x0[e] * w[e][0] - RT3I * dotv * w[e][3];

        // path (1,1,1): -1/sqrt2 * cross
        float cr0 = xv1[e] * sv2 - xv2[e] * sv1;
        float cr1 = xv2[e] * sv0 - xv0[e] * sv2;
        float cr2 = xv0[e] * sv1 - xv1[e] * sv0;

        // path (1,2,1): real CG(1,2,1) contraction
        float t50 =  A * xv0[e] * t22 + B * xv0[e] * t24 - B * xv1[e] * t21 - B * xv2[e] * t20;
        float t51 = -B * xv0[e] * t21 - 2.f * A * xv1[e] * t22 - B * xv2[e] * t23;
        float t52 = -B * xv0[e] * t20 - B * xv1[e] * t23 + A * xv2[e] * t22 - B * xv2[e] * t24;

        float x0w1 = x0[e] * w[e][1];
        float s0w2 = s0 * w[e][2];
        float wn4  = -RT2I * w[e][4];
        float m1 = sv0 * x0w1 + xv0[e] * s0w2 + cr0 * wn4 + t50 * w[e][5];
        float m2 = sv1 * x0w1 + xv1[e] * s0w2 + cr1 * wn4 + t51 * w[e][5];
        float m3 = sv2 * x0w1 + xv2[e] * s0w2 + cr2 * wn4 + t52 * w[e][5];

        red_add_v4(g_raw + (size_t)dst[e] * 128 + lane * 4, m0, m1, m2, m3);
    }
}

// ---------------- layer 3 ----------------
__global__ void __launch_bounds__(256) k_layer3(
    const float* __restrict__ esh, const float* __restrict__ elen,
    const int* __restrict__ ei, int E)
{
    EDGE_BINS

    float x0[4], xv0[4], xv1[4], xv2[4];
    #pragma unroll
    for (int e = 0; e < 4; e++)
        gather_feat(src[e], lane, x0[e], xv0[e], xv1[e], xv2[e]);

    float w0[4], w1[4];
    #pragma unroll
    for (int e = 0; e < 4; e++) {
        const __half2* tb = g_tab3h + (size_t)bin[e] * 32 + lane;
        float2 a = __half22float2(__ldg(tb));
        float2 b = __half22float2(__ldg(tb + 32));
        w0[e] = vld[e] * fmaf(fr[e], b.x - a.x, a.x);
        w1[e] = vld[e] * fmaf(fr[e], b.y - a.y, a.y);
    }

    const float RT3I = 0.57735026918962576451f;
    #pragma unroll
    for (int e = 0; e < 4; e++) {
        const float* she = esh + (size_t)(e0 + e < E ? e0 + e : E - 1) * 9;
        float s0  = she[0];
        float sv0 = she[1], sv1 = she[2], sv2 = she[3];

        float dotv = xv0[e] * sv0 + xv1[e] * sv1 + xv2[e] * sv2;
        float m0 = x0[e] * s0 * w0[e] - RT3I * dotv * w1[e];

        red_add(g_h3 + (size_t)dst[e] * 32 + lane, m0);
    }
}

// ---------------- silu + graph pooling ----------------
__global__ void k_pool(const int* __restrict__ batch, int N)
{
    int t = blockIdx.x * blockDim.x + threadIdx.x;
    if (t >= N * 32) return;
    int n = t >> 5, c = t & 31;
    float h = g_h3[(size_t)n * 32 + c];
    float y = h / (1.f + __expf(-h));
    atomicAdd(&g_pool[__ldg(&batch[n]) * 32 + c], y);
}

// ---------------- head ----------------
__global__ void k_head(const float* __restrict__ Wo, const float* __restrict__ bo,
                       float* __restrict__ out)
{
    __shared__ float Ws[32 * 8];
    __shared__ float bs[8];
    int t = threadIdx.x;
    if (t < 256) Ws[t] = Wo[t];
    if (t < 8)   bs[t] = bo[t];
    __syncthreads();
    if (t < NGR) {
        float acc[8];
        #pragma unroll
        for (int j = 0; j < 8; j++) acc[j] = bs[j];
        #pragma unroll
        for (int k = 0; k < 32; k++) {
            float gv = g_pool[t * 32 + k];
            #pragma unroll
            for (int j = 0; j < 8; j++) acc[j] = fmaf(gv, Ws[k * 8 + j], acc[j]);
        }
        float mx = acc[0];
        #pragma unroll
        for (int j = 1; j < 8; j++) mx = fmaxf(mx, acc[j]);
        float sm = 0.f;
        #pragma unroll
        for (int j = 0; j < 8; j++) { acc[j] = __expf(acc[j] - mx); sm += acc[j]; }
        float inv = 1.f / sm;
        #pragma unroll
        for (int j = 0; j < 8; j++) out[t * 8 + j] = acc[j] * inv;
    }
}

// ---------------- host ----------------
extern "C" void kernel_launch(void* const* d_in, const int* in_sizes, int n_in,
                              void* d_out, int out_size)
{
    int ix, ish, ilen, iW1, ib1, iW2, ib2, iW3, ib3, iWo, ibo, iei, ibatch;
    if (n_in >= 13 && (long long)in_sizes[1] == 9LL * (long long)in_sizes[2]) {
        ix = 0; ish = 1; ilen = 2; iW1 = 3; ib1 = 4; iW2 = 5; ib2 = 6;
        iW3 = 7; ib3 = 8; iWo = 9; ibo = 10; iei = 11; ibatch = 12;
    } else {
        ix = 0; iei = 1; ish = 2; ilen = 3; ibatch = 4; iW1 = 5; ib1 = 6;
        iW2 = 7; ib2 = 8; iW3 = 9; ib3 = 10; iWo = 11; ibo = 12;
    }

    const float* x     = (const float*)d_in[ix];
    const float* esh   = (const float*)d_in[ish];
    const float* elen  = (const float*)d_in[ilen];
    const float* W1    = (const float*)d_in[iW1];
    const float* b1    = (const float*)d_in[ib1];
    const float* W2    = (const float*)d_in[iW2];
    const float* b2    = (const float*)d_in[ib2];
    const float* W3    = (const float*)d_in[iW3];
    const float* b3    = (const float*)d_in[ib3];
    const float* Wo    = (const float*)d_in[iWo];
    const float* bo    = (const float*)d_in[ibo];
    const int*   ei    = (const int*)d_in[iei];
    const int*   batch = (const int*)d_in[ibatch];

    int N = in_sizes[ix];
    int E = in_sizes[ilen];
    if (N > NMAX) N = NMAX;
    if (E > EMAX) E = EMAX;

    void *praw, *ph3, *ppool, *pt1, *pt2, *pt3;
    cudaGetSymbolAddress(&praw, g_raw);
    cudaGetSymbolAddress(&ph3, g_h3);
    cudaGetSymbolAddress(&ppool, g_pool);
    cudaGetSymbolAddress(&pt1, g_tab1h);
    cudaGetSymbolAddress(&pt2, g_tab2h);
    cudaGetSymbolAddress(&pt3, g_tab3h);

    int nwarps = (E + 3) / 4;
    int nbE = (nwarps * 32 + 255) / 256;
    int nbN = (N * 32 + 255) / 256;

    // Build radial-weight tables (cutoff folded in)
    k_tab_emb<<<(TB_ROWS * 10 + 255) / 256, 256>>>();
    k_tab_build_h<<<(TB_ROWS * 32 + 255) / 256, 256>>>(W1, b1, (__half2*)pt1, 64, 1);
    k_tab_build_h<<<(TB_ROWS * 96 + 255) / 256, 256>>>(W2, b2, (__half2*)pt2, 192, 3);
    k_tab_build_h<<<(TB_ROWS * 32 + 255) / 256, 256>>>(W3, b3, (__half2*)pt3, 64, 1);

    // Layer 1
    cudaMemsetAsync(praw, 0, (size_t)N * 128 * sizeof(float), 0);
    k_layer1<<<nbE, 256>>>(x, esh, elen, ei, E);
    k_normact<<<nbN, 256>>>(N, /*zero_raw=*/1);

    // Layer 2
    k_layer2<<<nbE, 256>>>(esh, elen, ei, E);
    k_normact<<<nbN, 256>>>(N, /*zero_raw=*/0);

    // Layer 3 + pooling + head
    cudaMemsetAsync(ph3, 0, (size_t)N * 32 * sizeof(float), 0);
    cudaMemsetAsync(ppool, 0, (size_t)NGR * 32 * sizeof(float), 0);
    k_layer3<<<nbE, 256>>>(esh, elen, ei, E);
    k_pool<<<nbN, 256>>>(batch, N);
    k_head<<<1, 256>>>(Wo, bo, (float*)d_out);
}

// round 9
// speedup vs baseline: 2.0211x; 1.1179x over previous
#include <cuda_runtime.h>
#include <cuda_fp16.h>
#include <math.h>
#include <stdint.h>

#define NMAX  50000
#define EMAX  800000
#define NGR   128

#define TB_BINS  3072          // bins over [0, 1.5), step 1/2048
#define TB_ROWS  (TB_BINS + 1) // guard row (nearest rounding can hit TB_BINS)
#define TB_SCALE 2048.0f
#define TB_DMAX  1.49951f

// ---------------- scratch (static device arrays: no allocations) ----------------
// g_raw layout: (N, 32 lanes, 4 comps) fp32  -> node stride 128 floats
__device__ float   g_raw[(size_t)NMAX * 128];
// g_act layout: (N, 32 lanes, 4 comps) fp16  -> node stride 64 half2
__device__ __half2 g_acth[(size_t)NMAX * 64];
__device__ float   g_h3 [(size_t)NMAX * 32];
__device__ float   g_pool[NGR * 32];

// radial-weight tables (cutoff folded in), fp16 path-paired
__device__ float   g_etab[TB_ROWS * 10];
__device__ float   g_ewt [TB_ROWS];
__device__ __half2 g_tab1h[(size_t)TB_ROWS * 32];   // [row][lane] = {path0, path1}
__device__ __half2 g_tab2h[(size_t)TB_ROWS * 96];   // [row][pp][lane] = {path2pp, path2pp+1}
__device__ __half2 g_tab3h[(size_t)TB_ROWS * 32];

// ---------------- helpers ----------------
__device__ __forceinline__ float sspf(float x) {
    return fmaxf(x, 0.f) + log1pf(__expf(-fabsf(x))) - 0.69314718055994530942f;
}
__device__ __forceinline__ void red_add(float* p, float v) {
    asm volatile("red.global.add.f32 [%0], %1;" :: "l"(p), "f"(v) : "memory");
}
__device__ __forceinline__ void red_add_v4(float* p, float a, float b, float c, float d) {
    asm volatile("red.global.add.v4.f32 [%0], {%1,%2,%3,%4};"
                 :: "l"(p), "f"(a), "f"(b), "f"(c), "f"(d) : "memory");
}
__device__ __forceinline__ float cutoff_w(float d) {
    float u = d * (1.0f / 1.5f);
    if (u >= 1.f) return 0.f;
    float u2v = u * u;
    float u6 = u2v * u2v * u2v;
    return 1.f + u6 * (-28.f + u * (48.f - 21.f * u));
}

// ---------------- table generation ----------------
__global__ void k_tab_emb()
{
    int t = blockIdx.x * blockDim.x + threadIdx.x;
    if (t < TB_ROWS) {
        float d = (float)t * (1.0f / TB_SCALE);
        g_ewt[t] = cutoff_w(d);
    }
    if (t < TB_ROWS * 10) {
        int r = t / 10, k = t - 10 * r;
        float d = (float)r * (1.0f / TB_SCALE);
        float mu = 0.7f + (float)k * 0.111111111111111111f;
        float dd = d - mu;
        g_etab[t] = __expf(-50.f * dd * dd);
    }
}

// builds half2 pair table: pair pp of a C-column weight matrix; npp = C/64
__global__ void k_tab_build_h(const float* __restrict__ W, const float* __restrict__ b,
                              __half2* __restrict__ out, int C, int npp)
{
    int t = blockIdx.x * blockDim.x + threadIdx.x;
    int per_row = npp * 32;
    if (t >= TB_ROWS * per_row) return;
    int r = t / per_row, rem = t - r * per_row;
    int pp = rem >> 5, lane = rem & 31;
    int c0 = (2 * pp) * 32 + lane;
    int c1 = (2 * pp + 1) * 32 + lane;
    float v0 = b[c0], v1 = b[c1];
    #pragma unroll
    for (int k = 0; k < 10; k++) {
        float e = g_etab[r * 10 + k];
        v0 = fmaf(e, W[k * C + c0], v0);
        v1 = fmaf(e, W[k * C + c1], v1);
    }
    float w = g_ewt[r];
    out[t] = __floats2half2_rn(v0 * w, v1 * w);
}

// ---------------- common per-warp edge prologue (nearest-bin) ----------------
#define EDGE_BINS                                                               \
    int warp = (blockIdx.x * blockDim.x + threadIdx.x) >> 5;                    \
    int lane = threadIdx.x & 31;                                                \
    int e0 = warp * 4;                                                          \
    if (e0 >= E) return;                                                        \
    int src[4], dst[4], bin[4];                                                 \
    float vld[4];                                                               \
    _Pragma("unroll")                                                           \
    for (int e = 0; e < 4; e++) {                                               \
        int idx = e0 + e;                                                       \
        bool v = idx < E;                                                       \
        int id2 = v ? idx : (E - 1);                                            \
        src[e] = ei[id2]; dst[e] = ei[E + id2];                                 \
        float d = elen[id2];                                                    \
        vld[e] = v ? 1.f : 0.f;                                                 \
        float tt = fminf(fmaxf(d, 0.f), TB_DMAX) * TB_SCALE;                    \
        bin[e] = (int)(tt + 0.5f);                                              \
    }

// fetch fp16 feature quad for (node, lane): {x0, xv0, xv1, xv2}
__device__ __forceinline__ void gather_feat(int node, int lane,
                                            float& x0, float& xv0, float& xv1, float& xv2)
{
    const uint2* p = (const uint2*)(g_acth + (size_t)node * 64 + lane * 2);
    uint2 raw = __ldg(p);
    __half2 h01 = *reinterpret_cast<__half2*>(&raw.x);
    __half2 h23 = *reinterpret_cast<__half2*>(&raw.y);
    float2 f01 = __half22float2(h01);
    float2 f23 = __half22float2(h23);
    x0 = f01.x; xv0 = f01.y; xv1 = f23.x; xv2 = f23.y;
}

// ---------------- layer 1 ----------------
__global__ void __launch_bounds__(256) k_layer1(
    const float* __restrict__ x, const float* __restrict__ esh,
    const float* __restrict__ elen, const int* __restrict__ ei, int E)
{
    EDGE_BINS

    float xs[4];
    #pragma unroll
    for (int e = 0; e < 4; e++) xs[e] = __ldg(&x[src[e]]) * vld[e];

    float w0[4], w1[4];
    #pragma unroll
    for (int e = 0; e < 4; e++) {
        float2 a = __half22float2(__ldg(g_tab1h + (size_t)bin[e] * 32 + lane));
        w0[e] = a.x; w1[e] = a.y;
    }

    #pragma unroll
    for (int e = 0; e < 4; e++) {
        const float* she = esh + (size_t)(e0 + e < E ? e0 + e : E - 1) * 9;
        float s0  = she[0];
        float sv0 = she[1], sv1 = she[2], sv2 = she[3];

        float xw0 = xs[e] * w0[e];
        float xw1 = xs[e] * w1[e];
        red_add_v4(g_raw + (size_t)dst[e] * 128 + lane * 4,
                   xw0 * s0, xw1 * sv0, xw1 * sv1, xw1 * sv2);
    }
}

// ---------------- norm-act: g_raw(f32) -> g_acth(f16), optionally zero g_raw ----------------
__global__ void k_normact(int N, int zero_raw)
{
    int t = blockIdx.x * blockDim.x + threadIdx.x;
    if (t >= N * 32) return;
    int n = t >> 5, c = t & 31;
    float4* ip = (float4*)(g_raw + (size_t)n * 128 + c * 4);
    float4 v = *ip;
    float nr = sqrtf(v.y * v.y + v.z * v.z + v.w * v.w + 1e-12f);
    float sc = sspf(nr) / nr;
    uint2 o;
    __half2 h01 = __floats2half2_rn(sspf(v.x), v.y * sc);
    __half2 h23 = __floats2half2_rn(v.z * sc, v.w * sc);
    o.x = *reinterpret_cast<unsigned*>(&h01);
    o.y = *reinterpret_cast<unsigned*>(&h23);
    *(uint2*)(g_acth + (size_t)n * 64 + c * 2) = o;
    if (zero_raw) *ip = make_float4(0.f, 0.f, 0.f, 0.f);
}

// ---------------- layer 2 ----------------
__global__ void __launch_bounds__(256) k_layer2(
    const float* __restrict__ esh, const float* __restrict__ elen,
    const int* __restrict__ ei, int E)
{
    EDGE_BINS

    float x0[4], xv0[4], xv1[4], xv2[4];
    #pragma unroll
    for (int e = 0; e < 4; e++)
        gather_feat(src[e], lane, x0[e], xv0[e], xv1[e], xv2[e]);

    float w[4][6];
    #pragma unroll
    for (int e = 0; e < 4; e++) {
        const __half2* tb = g_tab2h + (size_t)bin[e] * 96 + lane;
        #pragma unroll
        for (int pp = 0; pp < 3; pp++) {
            float2 a = __half22float2(__ldg(tb + pp * 32));
            w[e][2 * pp]     = vld[e] * a.x;
            w[e][2 * pp + 1] = vld[e] * a.y;
        }
    }

    const float RT3I = 0.57735026918962576451f;  // 1/sqrt(3)
    const float RT2I = 0.70710678118654752440f;  // 1/sqrt(2)
    const float A    = 0.31622776601683793320f;  // 1/sqrt(10)
    const float B    = 0.54772255750516611346f;  // sqrt(3/10)

    #pragma unroll
    for (int e = 0; e < 4; e++) {
        const float* she = esh + (size_t)(e0 + e < E ? e0 + e : E - 1) * 9;
        float s0  = she[0];
        float sv0 = she[1], sv1 = she[2], sv2 = she[3];
        float t20 = she[4], t21 = she[5], t22 = she[6];
        float t23 = she[7], t24 = she[8];

        // paths (0,0,0) + (1,1,0)
        float dotv = xv0[e] * sv0 + xv1[e] * sv1 + xv2[e] * sv2;
        float m0 = s0 * x0[e] * w[e][0] - RT3I * dotv * w[e][3];

        // path (1,1,1): -1/sqrt2 * cross
        float cr0 = xv1[e] * sv2 - xv2[e] * sv1;
        float cr1 = xv2[e] * sv0 - xv0[e] * sv2;
        float cr2 = xv0[e] * sv1 - xv1[e] * sv0;

        // path (1,2,1): real CG(1,2,1) contraction
        float t50 =  A * xv0[e] * t22 + B * xv0[e] * t24 - B * xv1[e] * t21 - B * xv2[e] * t20;
        float t51 = -B * xv0[e] * t21 - 2.f * A * xv1[e] * t22 - B * xv2[e] * t23;
        float t52 = -B * xv0[e] * t20 - B * xv1[e] * t23 + A * xv2[e] * t22 - B * xv2[e] * t24;

        float x0w1 = x0[e] * w[e][1];
        float s0w2 = s0 * w[e][2];
        float wn4  = -RT2I * w[e][4];
        float m1 = sv0 * x0w1 + xv0[e] * s0w2 + cr0 * wn4 + t50 * w[e][5];
        float m2 = sv1 * x0w1 + xv1[e] * s0w2 + cr1 * wn4 + t51 * w[e][5];
        float m3 = sv2 * x0w1 + xv2[e] * s0w2 + cr2 * wn4 + t52 * w[e][5];

        red_add_v4(g_raw + (size_t)dst[e] * 128 + lane * 4, m0, m1, m2, m3);
    }
}

// ---------------- layer 3 ----------------
__global__ void __launch_bounds__(256) k_layer3(
    const float* __restrict__ esh, const float* __restrict__ elen,
    const int* __restrict__ ei, int E)
{
    EDGE_BINS

    float x0[4], xv0[4], xv1[4], xv2[4];
    #pragma unroll
    for (int e = 0; e < 4; e++)
        gather_feat(src[e], lane, x0[e], xv0[e], xv1[e], xv2[e]);

    float w0[4], w1[4];
    #pragma unroll
    for (int e = 0; e < 4; e++) {
        float2 a = __half22float2(__ldg(g_tab3h + (size_t)bin[e] * 32 + lane));
        w0[e] = vld[e] * a.x;
        w1[e] = vld[e] * a.y;
    }

    const float RT3I = 0.57735026918962576451f;
    #pragma unroll
    for (int e = 0; e < 4; e++) {
        const float* she = esh + (size_t)(e0 + e < E ? e0 + e : E - 1) * 9;
        float s0  = she[0];
        float sv0 = she[1], sv1 = she[2], sv2 = she[3];

        float dotv = xv0[e] * sv0 + xv1[e] * sv1 + xv2[e] * sv2;
        float m0 = x0[e] * s0 * w0[e] - RT3I * dotv * w1[e];

        red_add(g_h3 + (size_t)dst[e] * 32 + lane, m0);
    }
}

// ---------------- silu + graph pooling ----------------
__global__ void k_pool(const int* __restrict__ batch, int N)
{
    int t = blockIdx.x * blockDim.x + threadIdx.x;
    if (t >= N * 32) return;
    int n = t >> 5, c = t & 31;
    float h = g_h3[(size_t)n * 32 + c];
    float y = h / (1.f + __expf(-h));
    atomicAdd(&g_pool[__ldg(&batch[n]) * 32 + c], y);
}

// ---------------- head ----------------
__global__ void k_head(const float* __restrict__ Wo, const float* __restrict__ bo,
                       float* __restrict__ out)
{
    __shared__ float Ws[32 * 8];
    __shared__ float bs[8];
    int t = threadIdx.x;
    if (t < 256) Ws[t] = Wo[t];
    if (t < 8)   bs[t] = bo[t];
    __syncthreads();
    if (t < NGR) {
        float acc[8];
        #pragma unroll
        for (int j = 0; j < 8; j++) acc[j] = bs[j];
        #pragma unroll
        for (int k = 0; k < 32; k++) {
            float gv = g_pool[t * 32 + k];
            #pragma unroll
            for (int j = 0; j < 8; j++) acc[j] = fmaf(gv, Ws[k * 8 + j], acc[j]);
        }
        float mx = acc[0];
        #pragma unroll
        for (int j = 1; j < 8; j++) mx = fmaxf(mx, acc[j]);
        float sm = 0.f;
        #pragma unroll
        for (int j = 0; j < 8; j++) { acc[j] = __expf(acc[j] - mx); sm += acc[j]; }
        float inv = 1.f / sm;
        #pragma unroll
        for (int j = 0; j < 8; j++) out[t * 8 + j] = acc[j] * inv;
    }
}

// ---------------- host ----------------
extern "C" void kernel_launch(void* const* d_in, const int* in_sizes, int n_in,
                              void* d_out, int out_size)
{
    int ix, ish, ilen, iW1, ib1, iW2, ib2, iW3, ib3, iWo, ibo, iei, ibatch;
    if (n_in >= 13 && (long long)in_sizes[1] == 9LL * (long long)in_sizes[2]) {
        ix = 0; ish = 1; ilen = 2; iW1 = 3; ib1 = 4; iW2 = 5; ib2 = 6;
        iW3 = 7; ib3 = 8; iWo = 9; ibo = 10; iei = 11; ibatch = 12;
    } else {
        ix = 0; iei = 1; ish = 2; ilen = 3; ibatch = 4; iW1 = 5; ib1 = 6;
        iW2 = 7; ib2 = 8; iW3 = 9; ib3 = 10; iWo = 11; ibo = 12;
    }

    const float* x     = (const float*)d_in[ix];
    const float* esh   = (const float*)d_in[ish];
    const float* elen  = (const float*)d_in[ilen];
    const float* W1    = (const float*)d_in[iW1];
    const float* b1    = (const float*)d_in[ib1];
    const float* W2    = (const float*)d_in[iW2];
    const float* b2    = (const float*)d_in[ib2];
    const float* W3    = (const float*)d_in[iW3];
    const float* b3    = (const float*)d_in[ib3];
    const float* Wo    = (const float*)d_in[iWo];
    const float* bo    = (const float*)d_in[ibo];
    const int*   ei    = (const int*)d_in[iei];
    const int*   batch = (const int*)d_in[ibatch];

    int N = in_sizes[ix];
    int E = in_sizes[ilen];
    if (N > NMAX) N = NMAX;
    if (E > EMAX) E = EMAX;

    void *praw, *ph3, *ppool, *pt1, *pt2, *pt3;
    cudaGetSymbolAddress(&praw, g_raw);
    cudaGetSymbolAddress(&ph3, g_h3);
    cudaGetSymbolAddress(&ppool, g_pool);
    cudaGetSymbolAddress(&pt1, g_tab1h);
    cudaGetSymbolAddress(&pt2, g_tab2h);
    cudaGetSymbolAddress(&pt3, g_tab3h);

    int nwarps = (E + 3) / 4;
    int nbE = (nwarps * 32 + 255) / 256;
    int nbN = (N * 32 + 255) / 256;

    // Build radial-weight tables (cutoff folded in)
    k_tab_emb<<<(TB_ROWS * 10 + 255) / 256, 256>>>();
    k_tab_build_h<<<(TB_ROWS * 32 + 255) / 256, 256>>>(W1, b1, (__half2*)pt1, 64, 1);
    k_tab_build_h<<<(TB_ROWS * 96 + 255) / 256, 256>>>(W2, b2, (__half2*)pt2, 192, 3);
    k_tab_build_h<<<(TB_ROWS * 32 + 255) / 256, 256>>>(W3, b3, (__half2*)pt3, 64, 1);

    // Layer 1
    cudaMemsetAsync(praw, 0, (size_t)N * 128 * sizeof(float), 0);
    k_layer1<<<nbE, 256>>>(x, esh, elen, ei, E);
    k_normact<<<nbN, 256>>>(N, /*zero_raw=*/1);

    // Layer 2
    k_layer2<<<nbE, 256>>>(esh, elen, ei, E);
    k_normact<<<nbN, 256>>>(N, /*zero_raw=*/0);

    // Layer 3 + pooling + head
    cudaMemsetAsync(ph3, 0, (size_t)N * 32 * sizeof(float), 0);
    cudaMemsetAsync(ppool, 0, (size_t)NGR * 32 * sizeof(float), 0);
    k_layer3<<<nbE, 256>>>(esh, elen, ei, E);
    k_pool<<<nbN, 256>>>(batch, N);
    k_head<<<1, 256>>>(Wo, bo, (float*)d_out);
}

// round 10
// speedup vs baseline: 2.2397x; 1.1082x over previous
#include <cuda_runtime.h>
#include <cuda_fp16.h>
#include <math.h>
#include <stdint.h>

#define NMAX  50000
#define EMAX  800000
#define NGR   128

#define TB_BINS  3072          // bins over [0, 1.5), step 1/2048
#define TB_ROWS  (TB_BINS + 1) // guard row (nearest rounding can hit TB_BINS)
#define TB_SCALE 2048.0f
#define TB_DMAX  1.49951f

#define SCAN_B 256

// ---------------- scratch (static device arrays: no allocations) ----------------
// node features (N, 32 lanes, 4 comps) fp16 -> node stride 64 half2; double buffered
__device__ __half2 g_actA[(size_t)NMAX * 64];
__device__ __half2 g_actB[(size_t)NMAX * 64];
__device__ float   g_pool[NGR * 32];

// CSR by dst
__device__ int g_cnt[NMAX];
__device__ int g_off[NMAX];
__device__ int g_pos[NMAX];
__device__ int g_eid[EMAX];
__device__ int g_bsum[SCAN_B];

// radial-weight tables (cutoff folded in), fp16 path-paired
__device__ float   g_etab[TB_ROWS * 10];
__device__ float   g_ewt [TB_ROWS];
__device__ __half2 g_tab1h[(size_t)TB_ROWS * 32];   // [row][lane] = {path0, path1}
__device__ __half2 g_tab2h[(size_t)TB_ROWS * 96];   // [row][pp][lane]
__device__ __half2 g_tab3h[(size_t)TB_ROWS * 32];

// ---------------- helpers ----------------
__device__ __forceinline__ float sspf(float x) {
    return fmaxf(x, 0.f) + log1pf(__expf(-fabsf(x))) - 0.69314718055994530942f;
}
__device__ __forceinline__ float cutoff_w(float d) {
    float u = d * (1.0f / 1.5f);
    if (u >= 1.f) return 0.f;
    float u2v = u * u;
    float u6 = u2v * u2v * u2v;
    return 1.f + u6 * (-28.f + u * (48.f - 21.f * u));
}

// ---------------- table generation ----------------
__global__ void k_tab_emb()
{
    int t = blockIdx.x * blockDim.x + threadIdx.x;
    if (t < TB_ROWS) {
        float d = (float)t * (1.0f / TB_SCALE);
        g_ewt[t] = cutoff_w(d);
    }
    if (t < TB_ROWS * 10) {
        int r = t / 10, k = t - 10 * r;
        float d = (float)r * (1.0f / TB_SCALE);
        float mu = 0.7f + (float)k * 0.111111111111111111f;
        float dd = d - mu;
        g_etab[t] = __expf(-50.f * dd * dd);
    }
}

__global__ void k_tab_build_h(const float* __restrict__ W, const float* __restrict__ b,
                              __half2* __restrict__ out, int C, int npp)
{
    int t = blockIdx.x * blockDim.x + threadIdx.x;
    int per_row = npp * 32;
    if (t >= TB_ROWS * per_row) return;
    int r = t / per_row, rem = t - r * per_row;
    int pp = rem >> 5, lane = rem & 31;
    int c0 = (2 * pp) * 32 + lane;
    int c1 = (2 * pp + 1) * 32 + lane;
    float v0 = b[c0], v1 = b[c1];
    #pragma unroll
    for (int k = 0; k < 10; k++) {
        float e = g_etab[r * 10 + k];
        v0 = fmaf(e, W[k * C + c0], v0);
        v1 = fmaf(e, W[k * C + c1], v1);
    }
    float w = g_ewt[r];
    out[t] = __floats2half2_rn(v0 * w, v1 * w);
}

// ---------------- CSR build ----------------
__global__ void k_hist(const int* __restrict__ ei, int E)
{
    int e = blockIdx.x * blockDim.x + threadIdx.x;
    if (e < E) atomicAdd(&g_cnt[ei[E + e]], 1);
}

__global__ void k_scan1(int n)   // g_cnt -> g_off (block-exclusive), g_bsum[b] = block total
{
    __shared__ int sh[SCAN_B];
    int gid = blockIdx.x * SCAN_B + threadIdx.x;
    int v = (gid < n) ? g_cnt[gid] : 0;
    sh[threadIdx.x] = v;
    __syncthreads();
    #pragma unroll
    for (int ofs = 1; ofs < SCAN_B; ofs <<= 1) {
        int t = (threadIdx.x >= ofs) ? sh[threadIdx.x - ofs] : 0;
        __syncthreads();
        sh[threadIdx.x] += t;
        __syncthreads();
    }
    if (gid < n) g_off[gid] = sh[threadIdx.x] - v;
    if (threadIdx.x == SCAN_B - 1) g_bsum[blockIdx.x] = sh[SCAN_B - 1];
}

__global__ void k_scan2(int nb)  // exclusive scan of block sums (nb <= SCAN_B)
{
    __shared__ int sh[SCAN_B];
    int v = (threadIdx.x < nb) ? g_bsum[threadIdx.x] : 0;
    sh[threadIdx.x] = v;
    __syncthreads();
    #pragma unroll
    for (int ofs = 1; ofs < SCAN_B; ofs <<= 1) {
        int t = (threadIdx.x >= ofs) ? sh[threadIdx.x - ofs] : 0;
        __syncthreads();
        sh[threadIdx.x] += t;
        __syncthreads();
    }
    if (threadIdx.x < nb) g_bsum[threadIdx.x] = sh[threadIdx.x] - v;
}

__global__ void k_scan3(int n)   // add block offsets; copy to g_pos
{
    int gid = blockIdx.x * SCAN_B + threadIdx.x;
    if (gid < n) {
        int o = g_off[gid] + g_bsum[blockIdx.x];
        g_off[gid] = o;
        g_pos[gid] = o;
    }
}

__global__ void k_scatter(const int* __restrict__ ei, int E)
{
    int e = blockIdx.x * blockDim.x + threadIdx.x;
    if (e < E) {
        int d = ei[E + e];
        int p = atomicAdd(&g_pos[d], 1);
        g_eid[p] = e;
    }
}

// ---------------- per-edge uniform prologue (inside node loop) ----------------
#define EDGE_FETCH(i)                                                           \
    int eid  = __ldg(&g_eid[i]);                                                \
    int srcn = __ldg(&ei[eid]);                                                 \
    float dd = __ldg(&elen[eid]);                                               \
    float tt = fminf(fmaxf(dd, 0.f), TB_DMAX) * TB_SCALE;                       \
    int bin  = (int)(tt + 0.5f);                                                \
    const float* she = esh + (size_t)eid * 9;

// fetch fp16 feature quad for (node, lane): {x0, xv0, xv1, xv2}
__device__ __forceinline__ void gather_feat(const __half2* base, int node, int lane,
                                            float& x0, float& xv0, float& xv1, float& xv2)
{
    const uint2* p = (const uint2*)(base + (size_t)node * 64 + lane * 2);
    uint2 raw = __ldg(p);
    __half2 h01 = *reinterpret_cast<__half2*>(&raw.x);
    __half2 h23 = *reinterpret_cast<__half2*>(&raw.y);
    float2 f01 = __half22float2(h01);
    float2 f23 = __half22float2(h23);
    x0 = f01.x; xv0 = f01.y; xv1 = f23.x; xv2 = f23.y;
}

// write fp16 feature quad with norm-act applied
__device__ __forceinline__ void write_normact(__half2* base, int node, int lane,
                                              float s, float v0, float v1, float v2)
{
    float nr = sqrtf(v0 * v0 + v1 * v1 + v2 * v2 + 1e-12f);
    float sc = sspf(nr) / nr;
    uint2 o;
    __half2 h01 = __floats2half2_rn(sspf(s), v0 * sc);
    __half2 h23 = __floats2half2_rn(v1 * sc, v2 * sc);
    o.x = *reinterpret_cast<unsigned*>(&h01);
    o.y = *reinterpret_cast<unsigned*>(&h23);
    *(uint2*)(base + (size_t)node * 64 + lane * 2) = o;
}

// ---------------- layer 1 (dst-major, fused norm-act) ----------------
__global__ void __launch_bounds__(256) k_layer1(
    const float* __restrict__ x, const float* __restrict__ esh,
    const float* __restrict__ elen, const int* __restrict__ ei, int E, int N)
{
    int node = (blockIdx.x * blockDim.x + threadIdx.x) >> 5;
    if (node >= N) return;
    int lane = threadIdx.x & 31;
    int beg = __ldg(&g_off[node]);
    int end = (node + 1 < N) ? __ldg(&g_off[node + 1]) : E;

    float a0 = 0.f, a1 = 0.f, a2 = 0.f, a3 = 0.f;
    #pragma unroll 2
    for (int i = beg; i < end; i++) {
        EDGE_FETCH(i)
        float xs = __ldg(&x[srcn]);
        float2 wv = __half22float2(__ldg(g_tab1h + (size_t)bin * 32 + lane));
        float s0  = __ldg(she + 0);
        float sv0 = __ldg(she + 1), sv1 = __ldg(she + 2), sv2 = __ldg(she + 3);
        float xw0 = xs * wv.x;
        float xw1 = xs * wv.y;
        a0 += xw0 * s0;
        a1 += xw1 * sv0;
        a2 += xw1 * sv1;
        a3 += xw1 * sv2;
    }
    write_normact(g_actA, node, lane, a0, a1, a2, a3);
}

// ---------------- layer 2 (dst-major, fused norm-act) ----------------
__global__ void __launch_bounds__(256) k_layer2(
    const float* __restrict__ esh, const float* __restrict__ elen,
    const int* __restrict__ ei, int E, int N)
{
    int node = (blockIdx.x * blockDim.x + threadIdx.x) >> 5;
    if (node >= N) return;
    int lane = threadIdx.x & 31;
    int beg = __ldg(&g_off[node]);
    int end = (node + 1 < N) ? __ldg(&g_off[node + 1]) : E;

    const float RT3I = 0.57735026918962576451f;  // 1/sqrt(3)
    const float RT2I = 0.70710678118654752440f;  // 1/sqrt(2)
    const float A    = 0.31622776601683793320f;  // 1/sqrt(10)
    const float B    = 0.54772255750516611346f;  // sqrt(3/10)

    float a0 = 0.f, a1 = 0.f, a2 = 0.f, a3 = 0.f;
    #pragma unroll 2
    for (int i = beg; i < end; i++) {
        EDGE_FETCH(i)
        float x0, xv0, xv1, xv2;
        gather_feat(g_actA, srcn, lane, x0, xv0, xv1, xv2);

        const __half2* tb = g_tab2h + (size_t)bin * 96 + lane;
        float2 w01 = __half22float2(__ldg(tb));
        float2 w23 = __half22float2(__ldg(tb + 32));
        float2 w45 = __half22float2(__ldg(tb + 64));

        float s0  = __ldg(she + 0);
        float sv0 = __ldg(she + 1), sv1 = __ldg(she + 2), sv2 = __ldg(she + 3);
        float t20 = __ldg(she + 4), t21 = __ldg(she + 5), t22 = __ldg(she + 6);
        float t23 = __ldg(she + 7), t24 = __ldg(she + 8);

        // paths (0,0,0) + (1,1,0)
        float dotv = xv0 * sv0 + xv1 * sv1 + xv2 * sv2;
        float m0 = s0 * x0 * w01.x - RT3I * dotv * w23.y;

        // path (1,1,1): -1/sqrt2 * cross
        float cr0 = xv1 * sv2 - xv2 * sv1;
        float cr1 = xv2 * sv0 - xv0 * sv2;
        float cr2 = xv0 * sv1 - xv1 * sv0;

        // path (1,2,1): real CG(1,2,1) contraction
        float t50 =  A * xv0 * t22 + B * xv0 * t24 - B * xv1 * t21 - B * xv2 * t20;
        float t51 = -B * xv0 * t21 - 2.f * A * xv1 * t22 - B * xv2 * t23;
        float t52 = -B * xv0 * t20 - B * xv1 * t23 + A * xv2 * t22 - B * xv2 * t24;

        float x0w1 = x0 * w01.y;
        float s0w2 = s0 * w23.x;
        float wn4  = -RT2I * w45.x;
        a0 += m0;
        a1 += sv0 * x0w1 + xv0 * s0w2 + cr0 * wn4 + t50 * w45.y;
        a2 += sv1 * x0w1 + xv1 * s0w2 + cr1 * wn4 + t51 * w45.y;
        a3 += sv2 * x0w1 + xv2 * s0w2 + cr2 * wn4 + t52 * w45.y;
    }
    write_normact(g_actB, node, lane, a0, a1, a2, a3);
}

// ---------------- layer 3 (dst-major) + silu + pool ----------------
__global__ void __launch_bounds__(256) k_layer3(
    const float* __restrict__ esh, const float* __restrict__ elen,
    const int* __restrict__ ei, const int* __restrict__ batch, int E, int N)
{
    int node = (blockIdx.x * blockDim.x + threadIdx.x) >> 5;
    if (node >= N) return;
    int lane = threadIdx.x & 31;
    int beg = __ldg(&g_off[node]);
    int end = (node + 1 < N) ? __ldg(&g_off[node + 1]) : E;

    const float RT3I = 0.57735026918962576451f;
    float h = 0.f;
    #pragma unroll 2
    for (int i = beg; i < end; i++) {
        EDGE_FETCH(i)
        float x0, xv0, xv1, xv2;
        gather_feat(g_actB, srcn, lane, x0, xv0, xv1, xv2);
        float2 wv = __half22float2(__ldg(g_tab3h + (size_t)bin * 32 + lane));
        float s0  = __ldg(she + 0);
        float sv0 = __ldg(she + 1), sv1 = __ldg(she + 2), sv2 = __ldg(she + 3);
        float dotv = xv0 * sv0 + xv1 * sv1 + xv2 * sv2;
        h += x0 * s0 * wv.x - RT3I * dotv * wv.y;
    }
    float y = h / (1.f + __expf(-h));   // silu
    atomicAdd(&g_pool[__ldg(&batch[node]) * 32 + lane], y);
}

// ---------------- head ----------------
__global__ void k_head(const float* __restrict__ Wo, const float* __restrict__ bo,
                       float* __restrict__ out)
{
    __shared__ float Ws[32 * 8];
    __shared__ float bs[8];
    int t = threadIdx.x;
    if (t < 256) Ws[t] = Wo[t];
    if (t < 8)   bs[t] = bo[t];
    __syncthreads();
    if (t < NGR) {
        float acc[8];
        #pragma unroll
        for (int j = 0; j < 8; j++) acc[j] = bs[j];
        #pragma unroll
        for (int k = 0; k < 32; k++) {
            float gv = g_pool[t * 32 + k];
            #pragma unroll
            for (int j = 0; j < 8; j++) acc[j] = fmaf(gv, Ws[k * 8 + j], acc[j]);
        }
        float mx = acc[0];
        #pragma unroll
        for (int j = 1; j < 8; j++) mx = fmaxf(mx, acc[j]);
        float sm = 0.f;
        #pragma unroll
        for (int j = 0; j < 8; j++) { acc[j] = __expf(acc[j] - mx); sm += acc[j]; }
        float inv = 1.f / sm;
        #pragma unroll
        for (int j = 0; j < 8; j++) out[t * 8 + j] = acc[j] * inv;
    }
}

// ---------------- host ----------------
extern "C" void kernel_launch(void* const* d_in, const int* in_sizes, int n_in,
                              void* d_out, int out_size)
{
    int ix, ish, ilen, iW1, ib1, iW2, ib2, iW3, ib3, iWo, ibo, iei, ibatch;
    if (n_in >= 13 && (long long)in_sizes[1] == 9LL * (long long)in_sizes[2]) {
        ix = 0; ish = 1; ilen = 2; iW1 = 3; ib1 = 4; iW2 = 5; ib2 = 6;
        iW3 = 7; ib3 = 8; iWo = 9; ibo = 10; iei = 11; ibatch = 12;
    } else {
        ix = 0; iei = 1; ish = 2; ilen = 3; ibatch = 4; iW1 = 5; ib1 = 6;
        iW2 = 7; ib2 = 8; iW3 = 9; ib3 = 10; iWo = 11; ibo = 12;
    }

    const float* x     = (const float*)d_in[ix];
    const float* esh   = (const float*)d_in[ish];
    const float* elen  = (const float*)d_in[ilen];
    const float* W1    = (const float*)d_in[iW1];
    const float* b1    = (const float*)d_in[ib1];
    const float* W2    = (const float*)d_in[iW2];
    const float* b2    = (const float*)d_in[ib2];
    const float* W3    = (const float*)d_in[iW3];
    const float* b3    = (const float*)d_in[ib3];
    const float* Wo    = (const float*)d_in[iWo];
    const float* bo    = (const float*)d_in[ibo];
    const int*   ei    = (const int*)d_in[iei];
    const int*   batch = (const int*)d_in[ibatch];

    int N = in_sizes[ix];
    int E = in_sizes[ilen];
    if (N > NMAX) N = NMAX;
    if (E > EMAX) E = EMAX;

    void *pcnt, *ppool, *pt1, *pt2, *pt3;
    cudaGetSymbolAddress(&pcnt, g_cnt);
    cudaGetSymbolAddress(&ppool, g_pool);
    cudaGetSymbolAddress(&pt1, g_tab1h);
    cudaGetSymbolAddress(&pt2, g_tab2h);
    cudaGetSymbolAddress(&pt3, g_tab3h);

    int nbE  = (E + 255) / 256;
    int nbS  = (N + SCAN_B - 1) / SCAN_B;         // scan blocks (<= 196)
    int nbW  = (N * 32 + 255) / 256;              // warp-per-node kernels

    // Radial-weight tables (cutoff folded in)
    k_tab_emb<<<(TB_ROWS * 10 + 255) / 256, 256>>>();
    k_tab_build_h<<<(TB_ROWS * 32 + 255) / 256, 256>>>(W1, b1, (__half2*)pt1, 64, 1);
    k_tab_build_h<<<(TB_ROWS * 96 + 255) / 256, 256>>>(W2, b2, (__half2*)pt2, 192, 3);
    k_tab_build_h<<<(TB_ROWS * 32 + 255) / 256, 256>>>(W3, b3, (__half2*)pt3, 64, 1);

    // CSR by dst
    cudaMemsetAsync(pcnt, 0, (size_t)N * sizeof(int), 0);
    k_hist<<<nbE, 256>>>(ei, E);
    k_scan1<<<nbS, SCAN_B>>>(N);
    k_scan2<<<1, SCAN_B>>>(nbS);
    k_scan3<<<nbS, SCAN_B>>>(N);
    k_scatter<<<nbE, 256>>>(ei, E);

    // Layers (dst-major, fused norm-act)
    k_layer1<<<nbW, 256>>>(x, esh, elen, ei, E, N);
    k_layer2<<<nbW, 256>>>(esh, elen, ei, E, N);
    cudaMemsetAsync(ppool, 0, (size_t)NGR * 32 * sizeof(float), 0);
    k_layer3<<<nbW, 256>>>(esh, elen, ei, batch, E, N);
    k_head<<<1, 256>>>(Wo, bo, (float*)d_out);
}

// round 11
// speedup vs baseline: 2.3355x; 1.0428x over previous
#include <cuda_runtime.h>
#include <cuda_fp16.h>
#include <math.h>
#include <stdint.h>

#define NMAX  50000
#define EMAX  800000
#define NGR   128

#define TB_BINS  3072          // bins over [0, 1.5), step 1/2048
#define TB_ROWS  (TB_BINS + 1)
#define TB_SCALE 2048.0f
#define TB_DMAX  1.49951f

#define SCAN_B 256

// ---------------- scratch (static device arrays: no allocations) ----------------
// node features (N, 32 lanes, 4 comps) fp16 -> node stride 64 half2; double buffered
__device__ __half2 g_actA[(size_t)NMAX * 64];
__device__ __half2 g_actB[(size_t)NMAX * 64];
__device__ float   g_pool[NGR * 32];

// CSR by dst + packed edge records (CSR order)
// record = 12 floats: [srcn, bin, sh0, sh1 | sh2, sh3, x[srcn], sh4 | sh5, sh6, sh7, sh8]
__device__ int   g_cnt[NMAX];
__device__ int   g_off[NMAX];
__device__ int   g_pos[NMAX];
__device__ float g_erec[(size_t)EMAX * 12];
__device__ int   g_bsum[SCAN_B];

// radial-weight tables (cutoff folded in), fp16 path-paired
__device__ float   g_etab[TB_ROWS * 10];
__device__ float   g_ewt [TB_ROWS];
__device__ __half2 g_tab1h[(size_t)TB_ROWS * 32];
__device__ __half2 g_tab2h[(size_t)TB_ROWS * 96];
__device__ __half2 g_tab3h[(size_t)TB_ROWS * 32];

// ---------------- helpers ----------------
__device__ __forceinline__ float sspf(float x) {
    return fmaxf(x, 0.f) + log1pf(__expf(-fabsf(x))) - 0.69314718055994530942f;
}
__device__ __forceinline__ float cutoff_w(float d) {
    float u = d * (1.0f / 1.5f);
    if (u >= 1.f) return 0.f;
    float u2v = u * u;
    float u6 = u2v * u2v * u2v;
    return 1.f + u6 * (-28.f + u * (48.f - 21.f * u));
}

// ---------------- table generation ----------------
__global__ void k_tab_emb()
{
    int t = blockIdx.x * blockDim.x + threadIdx.x;
    if (t < TB_ROWS) {
        float d = (float)t * (1.0f / TB_SCALE);
        g_ewt[t] = cutoff_w(d);
    }
    if (t < TB_ROWS * 10) {
        int r = t / 10, k = t - 10 * r;
        float d = (float)r * (1.0f / TB_SCALE);
        float mu = 0.7f + (float)k * 0.111111111111111111f;
        float dd = d - mu;
        g_etab[t] = __expf(-50.f * dd * dd);
    }
}

__global__ void k_tab_build_h(const float* __restrict__ W, const float* __restrict__ b,
                              __half2* __restrict__ out, int C, int npp)
{
    int t = blockIdx.x * blockDim.x + threadIdx.x;
    int per_row = npp * 32;
    if (t >= TB_ROWS * per_row) return;
    int r = t / per_row, rem = t - r * per_row;
    int pp = rem >> 5, lane = rem & 31;
    int c0 = (2 * pp) * 32 + lane;
    int c1 = (2 * pp + 1) * 32 + lane;
    float v0 = b[c0], v1 = b[c1];
    #pragma unroll
    for (int k = 0; k < 10; k++) {
        float e = g_etab[r * 10 + k];
        v0 = fmaf(e, W[k * C + c0], v0);
        v1 = fmaf(e, W[k * C + c1], v1);
    }
    float w = g_ewt[r];
    out[t] = __floats2half2_rn(v0 * w, v1 * w);
}

// ---------------- CSR build ----------------
__global__ void k_hist(const int* __restrict__ ei, int E)
{
    int e = blockIdx.x * blockDim.x + threadIdx.x;
    if (e < E) atomicAdd(&g_cnt[ei[E + e]], 1);
}

__global__ void k_scan1(int n)
{
    __shared__ int sh[SCAN_B];
    int gid = blockIdx.x * SCAN_B + threadIdx.x;
    int v = (gid < n) ? g_cnt[gid] : 0;
    sh[threadIdx.x] = v;
    __syncthreads();
    #pragma unroll
    for (int ofs = 1; ofs < SCAN_B; ofs <<= 1) {
        int t = (threadIdx.x >= ofs) ? sh[threadIdx.x - ofs] : 0;
        __syncthreads();
        sh[threadIdx.x] += t;
        __syncthreads();
    }
    if (gid < n) g_off[gid] = sh[threadIdx.x] - v;
    if (threadIdx.x == SCAN_B - 1) g_bsum[blockIdx.x] = sh[SCAN_B - 1];
}

__global__ void k_scan2(int nb)
{
    __shared__ int sh[SCAN_B];
    int v = (threadIdx.x < nb) ? g_bsum[threadIdx.x] : 0;
    sh[threadIdx.x] = v;
    __syncthreads();
    #pragma unroll
    for (int ofs = 1; ofs < SCAN_B; ofs <<= 1) {
        int t = (threadIdx.x >= ofs) ? sh[threadIdx.x - ofs] : 0;
        __syncthreads();
        sh[threadIdx.x] += t;
        __syncthreads();
    }
    if (threadIdx.x < nb) g_bsum[threadIdx.x] = sh[threadIdx.x] - v;
}

__global__ void k_scan3(int n)
{
    int gid = blockIdx.x * SCAN_B + threadIdx.x;
    if (gid < n) {
        int o = g_off[gid] + g_bsum[blockIdx.x];
        g_off[gid] = o;
        g_pos[gid] = o;
    }
}

// scatter + build packed record at CSR slot
__global__ void k_scatter(const int* __restrict__ ei, const float* __restrict__ elen,
                          const float* __restrict__ esh, const float* __restrict__ x, int E)
{
    int e = blockIdx.x * blockDim.x + threadIdx.x;
    if (e >= E) return;
    int d = ei[E + e];
    int p = atomicAdd(&g_pos[d], 1);
    int s = ei[e];
    float dd = elen[e];
    float tt = fminf(fmaxf(dd, 0.f), TB_DMAX) * TB_SCALE;
    int bin = (int)(tt + 0.5f);
    const float* sh = esh + (size_t)e * 9;
    float4 r0 = make_float4(__int_as_float(s), __int_as_float(bin), sh[0], sh[1]);
    float4 r1 = make_float4(sh[2], sh[3], x[s], sh[4]);
    float4 r2 = make_float4(sh[5], sh[6], sh[7], sh[8]);
    float4* out = (float4*)(g_erec + (size_t)p * 12);
    out[0] = r0; out[1] = r1; out[2] = r2;
}

// ---------------- feature fetch / write ----------------
__device__ __forceinline__ void gather_feat(const __half2* base, int node, int lane,
                                            float& x0, float& xv0, float& xv1, float& xv2)
{
    const uint2* p = (const uint2*)(base + (size_t)node * 64 + lane * 2);
    uint2 raw = __ldg(p);
    __half2 h01 = *reinterpret_cast<__half2*>(&raw.x);
    __half2 h23 = *reinterpret_cast<__half2*>(&raw.y);
    float2 f01 = __half22float2(h01);
    float2 f23 = __half22float2(h23);
    x0 = f01.x; xv0 = f01.y; xv1 = f23.x; xv2 = f23.y;
}

__device__ __forceinline__ void write_normact(__half2* base, int node, int lane,
                                              float s, float v0, float v1, float v2)
{
    float nr = sqrtf(v0 * v0 + v1 * v1 + v2 * v2 + 1e-12f);
    float sc = sspf(nr) / nr;
    uint2 o;
    __half2 h01 = __floats2half2_rn(sspf(s), v0 * sc);
    __half2 h23 = __floats2half2_rn(v1 * sc, v2 * sc);
    o.x = *reinterpret_cast<unsigned*>(&h01);
    o.y = *reinterpret_cast<unsigned*>(&h23);
    *(uint2*)(base + (size_t)node * 64 + lane * 2) = o;
}

// ---------------- layer 1 (dst-major, fused norm-act; no gather needed) ----------------
__global__ void __launch_bounds__(256) k_layer1(int E, int N)
{
    int node = (blockIdx.x * blockDim.x + threadIdx.x) >> 5;
    if (node >= N) return;
    int lane = threadIdx.x & 31;
    int beg = __ldg(&g_off[node]);
    int end = (node + 1 < N) ? __ldg(&g_off[node + 1]) : E;

    float a0 = 0.f, a1 = 0.f, a2 = 0.f, a3 = 0.f;
    #pragma unroll 2
    for (int i = beg; i < end; i++) {
        const float4* rp = (const float4*)(g_erec + (size_t)i * 12);
        float4 r0 = __ldg(rp);
        float4 r1 = __ldg(rp + 1);
        int bin = __float_as_int(r0.y);
        float2 wv = __half22float2(__ldg(g_tab1h + (size_t)bin * 32 + lane));
        float xs = r1.z;
        float xw0 = xs * wv.x;
        float xw1 = xs * wv.y;
        a0 += xw0 * r0.z;    // s0
        a1 += xw1 * r0.w;    // sv0
        a2 += xw1 * r1.x;    // sv1
        a3 += xw1 * r1.y;    // sv2
    }
    write_normact(g_actA, node, lane, a0, a1, a2, a3);
}

// ---------------- layer 2 (dst-major, fused norm-act) ----------------
__global__ void __launch_bounds__(256) k_layer2(int E, int N)
{
    int node = (blockIdx.x * blockDim.x + threadIdx.x) >> 5;
    if (node >= N) return;
    int lane = threadIdx.x & 31;
    int beg = __ldg(&g_off[node]);
    int end = (node + 1 < N) ? __ldg(&g_off[node + 1]) : E;

    const float RT3I = 0.57735026918962576451f;  // 1/sqrt(3)
    const float RT2I = 0.70710678118654752440f;  // 1/sqrt(2)
    const float A    = 0.31622776601683793320f;  // 1/sqrt(10)
    const float B    = 0.54772255750516611346f;  // sqrt(3/10)

    float a0 = 0.f, a1 = 0.f, a2 = 0.f, a3 = 0.f;
    #pragma unroll 2
    for (int i = beg; i < end; i++) {
        const float4* rp = (const float4*)(g_erec + (size_t)i * 12);
        float4 r0 = __ldg(rp);
        float4 r1 = __ldg(rp + 1);
        float4 r2 = __ldg(rp + 2);
        int srcn = __float_as_int(r0.x);
        int bin  = __float_as_int(r0.y);

        float x0, xv0, xv1, xv2;
        gather_feat(g_actA, srcn, lane, x0, xv0, xv1, xv2);

        const __half2* tb = g_tab2h + (size_t)bin * 96 + lane;
        float2 w01 = __half22float2(__ldg(tb));
        float2 w23 = __half22float2(__ldg(tb + 32));
        float2 w45 = __half22float2(__ldg(tb + 64));

        float s0  = r0.z;
        float sv0 = r0.w, sv1 = r1.x, sv2 = r1.y;
        float t20 = r1.w, t21 = r2.x, t22 = r2.y, t23 = r2.z, t24 = r2.w;

        // paths (0,0,0) + (1,1,0)
        float dotv = xv0 * sv0 + xv1 * sv1 + xv2 * sv2;
        float m0 = s0 * x0 * w01.x - RT3I * dotv * w23.y;

        // path (1,1,1): -1/sqrt2 * cross
        float cr0 = xv1 * sv2 - xv2 * sv1;
        float cr1 = xv2 * sv0 - xv0 * sv2;
        float cr2 = xv0 * sv1 - xv1 * sv0;

        // path (1,2,1): real CG(1,2,1) contraction
        float t50 =  A * xv0 * t22 + B * xv0 * t24 - B * xv1 * t21 - B * xv2 * t20;
        float t51 = -B * xv0 * t21 - 2.f * A * xv1 * t22 - B * xv2 * t23;
        float t52 = -B * xv0 * t20 - B * xv1 * t23 + A * xv2 * t22 - B * xv2 * t24;

        float x0w1 = x0 * w01.y;
        float s0w2 = s0 * w23.x;
        float wn4  = -RT2I * w45.x;
        a0 += m0;
        a1 += sv0 * x0w1 + xv0 * s0w2 + cr0 * wn4 + t50 * w45.y;
        a2 += sv1 * x0w1 + xv1 * s0w2 + cr1 * wn4 + t51 * w45.y;
        a3 += sv2 * x0w1 + xv2 * s0w2 + cr2 * wn4 + t52 * w45.y;
    }
    write_normact(g_actB, node, lane, a0, a1, a2, a3);
}

// ---------------- layer 3 (dst-major) + silu + pool ----------------
__global__ void __launch_bounds__(256) k_layer3(const int* __restrict__ batch, int E, int N)
{
    int node = (blockIdx.x * blockDim.x + threadIdx.x) >> 5;
    if (node >= N) return;
    int lane = threadIdx.x & 31;
    int beg = __ldg(&g_off[node]);
    int end = (node + 1 < N) ? __ldg(&g_off[node + 1]) : E;

    const float RT3I = 0.57735026918962576451f;
    float h = 0.f;
    #pragma unroll 2
    for (int i = beg; i < end; i++) {
        const float4* rp = (const float4*)(g_erec + (size_t)i * 12);
        float4 r0 = __ldg(rp);
        float4 r1 = __ldg(rp + 1);
        int srcn = __float_as_int(r0.x);
        int bin  = __float_as_int(r0.y);

        float x0, xv0, xv1, xv2;
        gather_feat(g_actB, srcn, lane, x0, xv0, xv1, xv2);
        float2 wv = __half22float2(__ldg(g_tab3h + (size_t)bin * 32 + lane));

        float dotv = xv0 * r0.w + xv1 * r1.x + xv2 * r1.y;
        h += x0 * r0.z * wv.x - RT3I * dotv * wv.y;
    }
    float y = h / (1.f + __expf(-h));   // silu
    atomicAdd(&g_pool[__ldg(&batch[node]) * 32 + lane], y);
}

// ---------------- head ----------------
__global__ void k_head(const float* __restrict__ Wo, const float* __restrict__ bo,
                       float* __restrict__ out)
{
    __shared__ float Ws[32 * 8];
    __shared__ float bs[8];
    int t = threadIdx.x;
    if (t < 256) Ws[t] = Wo[t];
    if (t < 8)   bs[t] = bo[t];
    __syncthreads();
    if (t < NGR) {
        float acc[8];
        #pragma unroll
        for (int j = 0; j < 8; j++) acc[j] = bs[j];
        #pragma unroll
        for (int k = 0; k < 32; k++) {
            float gv = g_pool[t * 32 + k];
            #pragma unroll
            for (int j = 0; j < 8; j++) acc[j] = fmaf(gv, Ws[k * 8 + j], acc[j]);
        }
        float mx = acc[0];
        #pragma unroll
        for (int j = 1; j < 8; j++) mx = fmaxf(mx, acc[j]);
        float sm = 0.f;
        #pragma unroll
        for (int j = 0; j < 8; j++) { acc[j] = __expf(acc[j] - mx); sm += acc[j]; }
        float inv = 1.f / sm;
        #pragma unroll
        for (int j = 0; j < 8; j++) out[t * 8 + j] = acc[j] * inv;
    }
}

// ---------------- host ----------------
extern "C" void kernel_launch(void* const* d_in, const int* in_sizes, int n_in,
                              void* d_out, int out_size)
{
    int ix, ish, ilen, iW1, ib1, iW2, ib2, iW3, ib3, iWo, ibo, iei, ibatch;
    if (n_in >= 13 && (long long)in_sizes[1] == 9LL * (long long)in_sizes[2]) {
        ix = 0; ish = 1; ilen = 2; iW1 = 3; ib1 = 4; iW2 = 5; ib2 = 6;
        iW3 = 7; ib3 = 8; iWo = 9; ibo = 10; iei = 11; ibatch = 12;
    } else {
        ix = 0; iei = 1; ish = 2; ilen = 3; ibatch = 4; iW1 = 5; ib1 = 6;
        iW2 = 7; ib2 = 8; iW3 = 9; ib3 = 10; iWo = 11; ibo = 12;
    }

    const float* x     = (const float*)d_in[ix];
    const float* esh   = (const float*)d_in[ish];
    const float* elen  = (const float*)d_in[ilen];
    const float* W1    = (const float*)d_in[iW1];
    const float* b1    = (const float*)d_in[ib1];
    const float* W2    = (const float*)d_in[iW2];
    const float* b2    = (const float*)d_in[ib2];
    const float* W3    = (const float*)d_in[iW3];
    const float* b3    = (const float*)d_in[ib3];
    const float* Wo    = (const float*)d_in[iWo];
    const float* bo    = (const float*)d_in[ibo];
    const int*   ei    = (const int*)d_in[iei];
    const int*   batch = (const int*)d_in[ibatch];

    int N = in_sizes[ix];
    int E = in_sizes[ilen];
    if (N > NMAX) N = NMAX;
    if (E > EMAX) E = EMAX;

    void *pcnt, *ppool, *pt1, *pt2, *pt3;
    cudaGetSymbolAddress(&pcnt, g_cnt);
    cudaGetSymbolAddress(&ppool, g_pool);
    cudaGetSymbolAddress(&pt1, g_tab1h);
    cudaGetSymbolAddress(&pt2, g_tab2h);
    cudaGetSymbolAddress(&pt3, g_tab3h);

    int nbE = (E + 255) / 256;
    int nbS = (N + SCAN_B - 1) / SCAN_B;
    int nbW = (N * 32 + 255) / 256;

    // Radial-weight tables (cutoff folded in)
    k_tab_emb<<<(TB_ROWS * 10 + 255) / 256, 256>>>();
    k_tab_build_h<<<(TB_ROWS * 32 + 255) / 256, 256>>>(W1, b1, (__half2*)pt1, 64, 1);
    k_tab_build_h<<<(TB_ROWS * 96 + 255) / 256, 256>>>(W2, b2, (__half2*)pt2, 192, 3);
    k_tab_build_h<<<(TB_ROWS * 32 + 255) / 256, 256>>>(W3, b3, (__half2*)pt3, 64, 1);

    // CSR by dst + packed records
    cudaMemsetAsync(pcnt, 0, (size_t)N * sizeof(int), 0);
    k_hist<<<nbE, 256>>>(ei, E);
    k_scan1<<<nbS, SCAN_B>>>(N);
    k_scan2<<<1, SCAN_B>>>(nbS);
    k_scan3<<<nbS, SCAN_B>>>(N);
    k_scatter<<<nbE, 256>>>(ei, elen, esh, x, E);

    // Layers (dst-major, fused norm-act)
    k_layer1<<<nbW, 256>>>(E, N);
    k_layer2<<<nbW, 256>>>(E, N);
    cudaMemsetAsync(ppool, 0, (size_t)NGR * 32 * sizeof(float), 0);
    k_layer3<<<nbW, 256>>>(batch, E, N);
    k_head<<<1, 256>>>(Wo, bo, (float*)d_out);
}

// round 12
// speedup vs baseline: 2.4989x; 1.0699x over previous
#include <cuda_runtime.h>
#include <cuda_fp16.h>
#include <math.h>
#include <stdint.h>

#define NMAX  50000
#define EMAX  800000
#define NGR   128

#define TB_BINS  3072          // bins over [0, 1.5), step 1/2048
#define TB_ROWS  (TB_BINS + 1)
#define TB_SCALE 2048.0f
#define TB_DMAX  1.49951f

#define SCAN_B 256

// ---------------- scratch (static device arrays: no allocations) ----------------
// node features (N, 32 lanes, 4 comps) fp16 -> node stride 64 half2; double buffered
__device__ __half2 g_actA[(size_t)NMAX * 64];
__device__ __half2 g_actB[(size_t)NMAX * 64];
__device__ float   g_pool[NGR * 32];

// CSR by dst + packed edge records (CSR order), 32B each:
// u0 = { srcn, bin|xs<<16, h2(sh0,sh1), h2(sh2,sh3) }
// u1 = { h2(sh4,sh5), h2(sh6,sh7), h2(sh8,0), 0 }
__device__ int      g_cnt[NMAX];
__device__ int      g_off[NMAX];
__device__ int      g_pos[NMAX];
__device__ unsigned g_erec[(size_t)EMAX * 8];
__device__ int      g_bsum[SCAN_B];

// radial-weight tables (cutoff folded in), fp16 path-paired
__device__ float   g_etab[TB_ROWS * 10];
__device__ float   g_ewt [TB_ROWS];
__device__ __half2 g_tab1h[(size_t)TB_ROWS * 32];
__device__ __half2 g_tab2h[(size_t)TB_ROWS * 96];
__device__ __half2 g_tab3h[(size_t)TB_ROWS * 32];

// ---------------- helpers ----------------
__device__ __forceinline__ float sspf(float x) {
    return fmaxf(x, 0.f) + log1pf(__expf(-fabsf(x))) - 0.69314718055994530942f;
}
__device__ __forceinline__ float cutoff_w(float d) {
    float u = d * (1.0f / 1.5f);
    if (u >= 1.f) return 0.f;
    float u2v = u * u;
    float u6 = u2v * u2v * u2v;
    return 1.f + u6 * (-28.f + u * (48.f - 21.f * u));
}
__device__ __forceinline__ float2 h2f(unsigned bits) {
    __half2 h = *reinterpret_cast<__half2*>(&bits);
    return __half22float2(h);
}

// ---------------- table generation ----------------
__global__ void k_tab_emb()
{
    int t = blockIdx.x * blockDim.x + threadIdx.x;
    if (t < TB_ROWS) {
        float d = (float)t * (1.0f / TB_SCALE);
        g_ewt[t] = cutoff_w(d);
    }
    if (t < TB_ROWS * 10) {
        int r = t / 10, k = t - 10 * r;
        float d = (float)r * (1.0f / TB_SCALE);
        float mu = 0.7f + (float)k * 0.111111111111111111f;
        float dd = d - mu;
        g_etab[t] = __expf(-50.f * dd * dd);
    }
}

// one kernel builds all three tables; per_row = 32(t1) + 96(t2) + 32(t3) = 160
__global__ void k_tab_build_all(
    const float* __restrict__ W1, const float* __restrict__ b1,
    const float* __restrict__ W2, const float* __restrict__ b2,
    const float* __restrict__ W3, const float* __restrict__ b3)
{
    int t = blockIdx.x * blockDim.x + threadIdx.x;
    if (t >= TB_ROWS * 160) return;
    int r = t / 160, rem = t - r * 160;

    const float* W; const float* b; __half2* out; int C; int pp; int lane; int oidx;
    if (rem < 32)       { W = W1; b = b1; C = 64;  pp = 0;                 lane = rem;        out = g_tab1h; oidx = r * 32 + rem; }
    else if (rem < 128) { W = W2; b = b2; C = 192; pp = (rem - 32) >> 5;   lane = rem & 31;   out = g_tab2h; oidx = r * 96 + (rem - 32); }
    else                { W = W3; b = b3; C = 64;  pp = 0;                 lane = rem & 31;   out = g_tab3h; oidx = r * 32 + (rem - 128); }

    int c0 = (2 * pp) * 32 + lane;
    int c1 = (2 * pp + 1) * 32 + lane;
    float v0 = b[c0], v1 = b[c1];
    #pragma unroll
    for (int k = 0; k < 10; k++) {
        float e = g_etab[r * 10 + k];
        v0 = fmaf(e, W[k * C + c0], v0);
        v1 = fmaf(e, W[k * C + c1], v1);
    }
    float w = g_ewt[r];
    out[oidx] = __floats2half2_rn(v0 * w, v1 * w);
}

// ---------------- CSR build ----------------
__global__ void k_hist(const int* __restrict__ ei, int E)
{
    int e = blockIdx.x * blockDim.x + threadIdx.x;
    if (e < E) atomicAdd(&g_cnt[ei[E + e]], 1);
}

__global__ void k_scan1(int n)
{
    __shared__ int sh[SCAN_B];
    int gid = blockIdx.x * SCAN_B + threadIdx.x;
    int v = (gid < n) ? g_cnt[gid] : 0;
    sh[threadIdx.x] = v;
    __syncthreads();
    #pragma unroll
    for (int ofs = 1; ofs < SCAN_B; ofs <<= 1) {
        int t = (threadIdx.x >= ofs) ? sh[threadIdx.x - ofs] : 0;
        __syncthreads();
        sh[threadIdx.x] += t;
        __syncthreads();
    }
    if (gid < n) g_off[gid] = sh[threadIdx.x] - v;
    if (threadIdx.x == SCAN_B - 1) g_bsum[blockIdx.x] = sh[SCAN_B - 1];
}

__global__ void k_scan2(int nb)
{
    __shared__ int sh[SCAN_B];
    int v = (threadIdx.x < nb) ? g_bsum[threadIdx.x] : 0;
    sh[threadIdx.x] = v;
    __syncthreads();
    #pragma unroll
    for (int ofs = 1; ofs < SCAN_B; ofs <<= 1) {
        int t = (threadIdx.x >= ofs) ? sh[threadIdx.x - ofs] : 0;
        __syncthreads();
        sh[threadIdx.x] += t;
        __syncthreads();
    }
    if (threadIdx.x < nb) g_bsum[threadIdx.x] = sh[threadIdx.x] - v;
}

__global__ void k_scan3(int n)
{
    int gid = blockIdx.x * SCAN_B + threadIdx.x;
    if (gid < n) {
        int o = g_off[gid] + g_bsum[blockIdx.x];
        g_off[gid] = o;
        g_pos[gid] = o;
    }
}

// scatter + build packed 32B record at CSR slot
__global__ void k_scatter(const int* __restrict__ ei, const float* __restrict__ elen,
                          const float* __restrict__ esh, const float* __restrict__ x, int E)
{
    int e = blockIdx.x * blockDim.x + threadIdx.x;
    if (e >= E) return;
    int d = ei[E + e];
    int p = atomicAdd(&g_pos[d], 1);
    int s = ei[e];
    float dd = elen[e];
    float tt = fminf(fmaxf(dd, 0.f), TB_DMAX) * TB_SCALE;
    unsigned bin = (unsigned)(int)(tt + 0.5f);
    const float* sh = esh + (size_t)e * 9;

    __half xsh = __float2half_rn(x[s]);
    unsigned w1 = bin | ((unsigned)__half_as_ushort(xsh) << 16);
    __half2 p01 = __floats2half2_rn(sh[0], sh[1]);
    __half2 p23 = __floats2half2_rn(sh[2], sh[3]);
    __half2 p45 = __floats2half2_rn(sh[4], sh[5]);
    __half2 p67 = __floats2half2_rn(sh[6], sh[7]);
    __half2 p8z = __floats2half2_rn(sh[8], 0.f);

    uint4 u0 = make_uint4((unsigned)s, w1,
                          *reinterpret_cast<unsigned*>(&p01),
                          *reinterpret_cast<unsigned*>(&p23));
    uint4 u1 = make_uint4(*reinterpret_cast<unsigned*>(&p45),
                          *reinterpret_cast<unsigned*>(&p67),
                          *reinterpret_cast<unsigned*>(&p8z), 0u);
    uint4* out = (uint4*)(g_erec + (size_t)p * 8);
    out[0] = u0; out[1] = u1;
}

// ---------------- feature fetch / write ----------------
__device__ __forceinline__ void gather_feat(const __half2* base, int node, int lane,
                                            float& x0, float& xv0, float& xv1, float& xv2)
{
    const uint2* p = (const uint2*)(base + (size_t)node * 64 + lane * 2);
    uint2 raw = __ldg(p);
    float2 f01 = h2f(raw.x);
    float2 f23 = h2f(raw.y);
    x0 = f01.x; xv0 = f01.y; xv1 = f23.x; xv2 = f23.y;
}

__device__ __forceinline__ void write_normact(__half2* base, int node, int lane,
                                              float s, float v0, float v1, float v2)
{
    float nr = sqrtf(v0 * v0 + v1 * v1 + v2 * v2 + 1e-12f);
    float sc = sspf(nr) / nr;
    uint2 o;
    __half2 h01 = __floats2half2_rn(sspf(s), v0 * sc);
    __half2 h23 = __floats2half2_rn(v1 * sc, v2 * sc);
    o.x = *reinterpret_cast<unsigned*>(&h01);
    o.y = *reinterpret_cast<unsigned*>(&h23);
    *(uint2*)(base + (size_t)node * 64 + lane * 2) = o;
}

// ---------------- layer 1 (dst-major, fused norm-act; 1 record + 1 table load) ----------------
__global__ void __launch_bounds__(256) k_layer1(int E, int N)
{
    int node = (blockIdx.x * blockDim.x + threadIdx.x) >> 5;
    if (node >= N) return;
    int lane = threadIdx.x & 31;
    int beg = __ldg(&g_off[node]);
    int end = (node + 1 < N) ? __ldg(&g_off[node + 1]) : E;

    float a0 = 0.f, a1 = 0.f, a2 = 0.f, a3 = 0.f;
    #pragma unroll 2
    for (int i = beg; i < end; i++) {
        uint4 u0 = __ldg((const uint4*)(g_erec + (size_t)i * 8));
        int bin = (int)(u0.y & 0xFFFFu);
        float xs = __half2float(__ushort_as_half((unsigned short)(u0.y >> 16)));
        float2 s01 = h2f(u0.z);
        float2 s23 = h2f(u0.w);
        float2 wv = __half22float2(__ldg(g_tab1h + (size_t)bin * 32 + lane));
        float xw0 = xs * wv.x;
        float xw1 = xs * wv.y;
        a0 += xw0 * s01.x;
        a1 += xw1 * s01.y;
        a2 += xw1 * s23.x;
        a3 += xw1 * s23.y;
    }
    write_normact(g_actA, node, lane, a0, a1, a2, a3);
}

// ---------------- layer 2 (dst-major, fused norm-act) ----------------
__global__ void __launch_bounds__(256) k_layer2(int E, int N)
{
    int node = (blockIdx.x * blockDim.x + threadIdx.x) >> 5;
    if (node >= N) return;
    int lane = threadIdx.x & 31;
    int beg = __ldg(&g_off[node]);
    int end = (node + 1 < N) ? __ldg(&g_off[node + 1]) : E;

    const float RT3I = 0.57735026918962576451f;  // 1/sqrt(3)
    const float RT2I = 0.70710678118654752440f;  // 1/sqrt(2)
    const float A    = 0.31622776601683793320f;  // 1/sqrt(10)
    const float B    = 0.54772255750516611346f;  // sqrt(3/10)

    float a0 = 0.f, a1 = 0.f, a2 = 0.f, a3 = 0.f;
    #pragma unroll 2
    for (int i = beg; i < end; i++) {
        const uint4* rp = (const uint4*)(g_erec + (size_t)i * 8);
        uint4 u0 = __ldg(rp);
        uint4 u1 = __ldg(rp + 1);
        int srcn = (int)u0.x;
        int bin  = (int)(u0.y & 0xFFFFu);

        float x0, xv0, xv1, xv2;
        gather_feat(g_actA, srcn, lane, x0, xv0, xv1, xv2);

        const __half2* tb = g_tab2h + (size_t)bin * 96 + lane;
        float2 w01 = __half22float2(__ldg(tb));
        float2 w23 = __half22float2(__ldg(tb + 32));
        float2 w45 = __half22float2(__ldg(tb + 64));

        float2 s01 = h2f(u0.z);
        float2 s23 = h2f(u0.w);
        float2 s45 = h2f(u1.x);
        float2 s67 = h2f(u1.y);
        float2 s8z = h2f(u1.z);
        float s0  = s01.x;
        float sv0 = s01.y, sv1 = s23.x, sv2 = s23.y;
        float t20 = s45.x, t21 = s45.y, t22 = s67.x, t23 = s67.y, t24 = s8z.x;

        // paths (0,0,0) + (1,1,0)
        float dotv = xv0 * sv0 + xv1 * sv1 + xv2 * sv2;
        float m0 = s0 * x0 * w01.x - RT3I * dotv * w23.y;

        // path (1,1,1): -1/sqrt2 * cross
        float cr0 = xv1 * sv2 - xv2 * sv1;
        float cr1 = xv2 * sv0 - xv0 * sv2;
        float cr2 = xv0 * sv1 - xv1 * sv0;

        // path (1,2,1): real CG(1,2,1) contraction
        float t50 =  A * xv0 * t22 + B * xv0 * t24 - B * xv1 * t21 - B * xv2 * t20;
        float t51 = -B * xv0 * t21 - 2.f * A * xv1 * t22 - B * xv2 * t23;
        float t52 = -B * xv0 * t20 - B * xv1 * t23 + A * xv2 * t22 - B * xv2 * t24;

        float x0w1 = x0 * w01.y;
        float s0w2 = s0 * w23.x;
        float wn4  = -RT2I * w45.x;
        a0 += m0;
        a1 += sv0 * x0w1 + xv0 * s0w2 + cr0 * wn4 + t50 * w45.y;
        a2 += sv1 * x0w1 + xv1 * s0w2 + cr1 * wn4 + t51 * w45.y;
        a3 += sv2 * x0w1 + xv2 * s0w2 + cr2 * wn4 + t52 * w45.y;
    }
    write_normact(g_actB, node, lane, a0, a1, a2, a3);
}

// ---------------- layer 3 (dst-major) + silu + pool ----------------
__global__ void __launch_bounds__(256) k_layer3(const int* __restrict__ batch, int E, int N)
{
    int node = (blockIdx.x * blockDim.x + threadIdx.x) >> 5;
    if (node >= N) return;
    int lane = threadIdx.x & 31;
    int beg = __ldg(&g_off[node]);
    int end = (node + 1 < N) ? __ldg(&g_off[node + 1]) : E;

    const float RT3I = 0.57735026918962576451f;
    float h = 0.f;
    #pragma unroll 2
    for (int i = beg; i < end; i++) {
        uint4 u0 = __ldg((const uint4*)(g_erec + (size_t)i * 8));
        int srcn = (int)u0.x;
        int bin  = (int)(u0.y & 0xFFFFu);

        float x0, xv0, xv1, xv2;
        gather_feat(g_actB, srcn, lane, x0, xv0, xv1, xv2);
        float2 wv = __half22float2(__ldg(g_tab3h + (size_t)bin * 32 + lane));

        float2 s01 = h2f(u0.z);
        float2 s23 = h2f(u0.w);
        float dotv = xv0 * s01.y + xv1 * s23.x + xv2 * s23.y;
        h += x0 * s01.x * wv.x - RT3I * dotv * wv.y;
    }
    float y = h / (1.f + __expf(-h));   // silu
    atomicAdd(&g_pool[__ldg(&batch[node]) * 32 + lane], y);
}

// ---------------- head ----------------
__global__ void k_head(const float* __restrict__ Wo, const float* __restrict__ bo,
                       float* __restrict__ out)
{
    __shared__ float Ws[32 * 8];
    __shared__ float bs[8];
    int t = threadIdx.x;
    if (t < 256) Ws[t] = Wo[t];
    if (t < 8)   bs[t] = bo[t];
    __syncthreads();
    if (t < NGR) {
        float acc[8];
        #pragma unroll
        for (int j = 0; j < 8; j++) acc[j] = bs[j];
        #pragma unroll
        for (int k = 0; k < 32; k++) {
            float gv = g_pool[t * 32 + k];
            #pragma unroll
            for (int j = 0; j < 8; j++) acc[j] = fmaf(gv, Ws[k * 8 + j], acc[j]);
        }
        float mx = acc[0];
        #pragma unroll
        for (int j = 1; j < 8; j++) mx = fmaxf(mx, acc[j]);
        float sm = 0.f;
        #pragma unroll
        for (int j = 0; j < 8; j++) { acc[j] = __expf(acc[j] - mx); sm += acc[j]; }
        float inv = 1.f / sm;
        #pragma unroll
        for (int j = 0; j < 8; j++) out[t * 8 + j] = acc[j] * inv;
    }
}

// ---------------- host ----------------
extern "C" void kernel_launch(void* const* d_in, const int* in_sizes, int n_in,
                              void* d_out, int out_size)
{
    int ix, ish, ilen, iW1, ib1, iW2, ib2, iW3, ib3, iWo, ibo, iei, ibatch;
    if (n_in >= 13 && (long long)in_sizes[1] == 9LL * (long long)in_sizes[2]) {
        ix = 0; ish = 1; ilen = 2; iW1 = 3; ib1 = 4; iW2 = 5; ib2 = 6;
        iW3 = 7; ib3 = 8; iWo = 9; ibo = 10; iei = 11; ibatch = 12;
    } else {
        ix = 0; iei = 1; ish = 2; ilen = 3; ibatch = 4; iW1 = 5; ib1 = 6;
        iW2 = 7; ib2 = 8; iW3 = 9; ib3 = 10; iWo = 11; ibo = 12;
    }

    const float* x     = (const float*)d_in[ix];
    const float* esh   = (const float*)d_in[ish];
    const float* elen  = (const float*)d_in[ilen];
    const float* W1    = (const float*)d_in[iW1];
    const float* b1    = (const float*)d_in[ib1];
    const float* W2    = (const float*)d_in[iW2];
    const float* b2    = (const float*)d_in[ib2];
    const float* W3    = (const float*)d_in[iW3];
    const float* b3    = (const float*)d_in[ib3];
    const float* Wo    = (const float*)d_in[iWo];
    const float* bo    = (const float*)d_in[ibo];
    const int*   ei    = (const int*)d_in[iei];
    const int*   batch = (const int*)d_in[ibatch];

    int N = in_sizes[ix];
    int E = in_sizes[ilen];
    if (N > NMAX) N = NMAX;
    if (E > EMAX) E = EMAX;

    void *pcnt, *ppool;
    cudaGetSymbolAddress(&pcnt, g_cnt);
    cudaGetSymbolAddress(&ppool, g_pool);

    int nbE = (E + 255) / 256;
    int nbS = (N + SCAN_B - 1) / SCAN_B;
    int nbW = (N * 32 + 255) / 256;

    // Radial-weight tables (cutoff folded in)
    k_tab_emb<<<(TB_ROWS * 10 + 255) / 256, 256>>>();
    k_tab_build_all<<<(TB_ROWS * 160 + 255) / 256, 256>>>(W1, b1, W2, b2, W3, b3);

    // CSR by dst + packed records
    cudaMemsetAsync(pcnt, 0, (size_t)N * sizeof(int), 0);
    k_hist<<<nbE, 256>>>(ei, E);
    k_scan1<<<nbS, SCAN_B>>>(N);
    k_scan2<<<1, SCAN_B>>>(nbS);
    k_scan3<<<nbS, SCAN_B>>>(N);
    k_scatter<<<nbE, 256>>>(ei, elen, esh, x, E);

    // Layers (dst-major, fused norm-act)
    k_layer1<<<nbW, 256>>>(E, N);
    k_layer2<<<nbW, 256>>>(E, N);
    cudaMemsetAsync(ppool, 0, (size_t)NGR * 32 * sizeof(float), 0);
    k_layer3<<<nbW, 256>>>(batch, E, N);
    k_head<<<1, 256>>>(Wo, bo, (float*)d_out);
}